// round 4
// baseline (speedup 1.0000x reference)
#include <cuda_runtime.h>
#include <cuda_bf16.h>
#include <math.h>

typedef __nv_bfloat16 bf16;
typedef long long ll;
typedef unsigned u32;

#define Bn 8
#define NMELS 128
#define TIN 4096
#define T1 2048
#define S 1024
#define D 1024
#define H 8
#define DH 128
#define Fdim 4096
#define NTOK (Bn*S)
#define Ldim 6

// ---------------- fp32 scratch ----------------
__device__ float g_h1[(size_t)Bn*T1*D];            // conv1 out [b][t][d]
__device__ float g_x [(size_t)NTOK*D];             // residual stream
__device__ float g_scores[(size_t)Bn*H*S*S];

// ---------------- bf16 hi/lo buffers ----------------
__device__ __align__(256) bf16 c1h[(size_t)D*384],  c1l[(size_t)D*384];
__device__ __align__(256) bf16 c2h[(size_t)D*3072], c2l[(size_t)D*3072];
__device__ __align__(256) bf16 wqh[(size_t)Ldim*D*D], wql[(size_t)Ldim*D*D];
__device__ __align__(256) bf16 wkh[(size_t)Ldim*D*D], wkl[(size_t)Ldim*D*D];
__device__ __align__(256) bf16 wvh[(size_t)Ldim*D*D], wvl[(size_t)Ldim*D*D];
__device__ __align__(256) bf16 woh[(size_t)Ldim*D*D], wol[(size_t)Ldim*D*D];
__device__ __align__(256) bf16 w1h[(size_t)Ldim*Fdim*D], w1l[(size_t)Ldim*Fdim*D];
__device__ __align__(256) bf16 w2h[(size_t)Ldim*Fdim*D], w2l[(size_t)Ldim*Fdim*D];
__device__ __align__(256) bf16 g_colh[(size_t)Bn*3072*S], g_coll[(size_t)Bn*3072*S];
__device__ __align__(256) bf16 g_yh[(size_t)NTOK*D], g_yl[(size_t)NTOK*D];
__device__ __align__(256) bf16 g_qh[(size_t)NTOK*D], g_ql[(size_t)NTOK*D];
__device__ __align__(256) bf16 g_kh[(size_t)NTOK*D], g_kl[(size_t)NTOK*D];
__device__ __align__(256) bf16 g_vth[(size_t)D*NTOK], g_vtl[(size_t)D*NTOK];
__device__ __align__(256) bf16 g_ph[(size_t)Bn*H*S*S], g_pl[(size_t)Bn*H*S*S];
__device__ __align__(256) bf16 g_m1h[(size_t)NTOK*Fdim], g_m1l[(size_t)NTOK*Fdim];
__device__ __align__(256) bf16 g_oh[(size_t)NTOK*D], g_ol[(size_t)NTOK*D];

// ---------------- helpers ----------------
__device__ __forceinline__ float gelu_exact(float v) {
    return 0.5f * v * (1.0f + erff(v * 0.70710678118654752f));
}
__device__ __forceinline__ void splitf(float v, bf16& h, bf16& l) {
    h = __float2bfloat16_rn(v);
    l = __float2bfloat16_rn(v - __bfloat162float(h));
}
__device__ __forceinline__ void mma_bf16(float* d, const u32* a, const u32* b) {
    asm volatile(
        "mma.sync.aligned.m16n8k16.row.col.f32.bf16.bf16.f32 "
        "{%0,%1,%2,%3}, {%4,%5,%6,%7}, {%8,%9}, {%0,%1,%2,%3};\n"
        : "+f"(d[0]), "+f"(d[1]), "+f"(d[2]), "+f"(d[3])
        : "r"(a[0]), "r"(a[1]), "r"(a[2]), "r"(a[3]), "r"(b[0]), "r"(b[1]));
}
__device__ __forceinline__ void ldsm4(u32* r, u32 addr) {
    asm volatile("ldmatrix.sync.aligned.m8n8.x4.shared.b16 {%0,%1,%2,%3}, [%4];\n"
        : "=r"(r[0]), "=r"(r[1]), "=r"(r[2]), "=r"(r[3]) : "r"(addr));
}
__device__ __forceinline__ void cpa16(u32 dst, const void* src) {
    asm volatile("cp.async.cg.shared.global [%0], [%1], 16;\n" :: "r"(dst), "l"(src));
}

// ---------------- bf16x3 tensor-core GEMM (mma.sync, 3-stage cp.async) ----------------
// C[M,N] = A[M,K] * B[N,K]^T
#define KC 32
#define NSTG 3
#define PAD 40
#define TILE_E (128*PAD)             // bf16 elems per smem operand tile
#define STG_B  (4*TILE_E*2)          // bytes per stage (Ah,Al,Bh,Bl) = 40960
#define SMEM_TOT (NSTG*STG_B)        // 122880

struct GemmP {
    const bf16 *Ah, *Al, *Bh, *Bl;
    float* C; bf16 *Ch, *Cl;
    const float* bias;
    int K, lda, ldb, ldc;
    int zDiv;
    ll sAo, sAi, sBo, sBi, sCo, sCi;
    int biasMode;   // 0 none, 1 per-col(n), 2 per-row(m)
    int addC;       // fp32 residual accumulate
    int act;        // 0 none, 1 exact GELU, 2 RoPE+scale (pairs of columns)
    int transStore; // store (m,n) at [n*ldc+m]
    int outF32, outBf;
};

__global__ __launch_bounds__(256, 1) void gemm_tc(GemmP p) {
    extern __shared__ __align__(16) bf16 sm[];
    int z = blockIdx.z;
    ll offA = (ll)(z / p.zDiv) * p.sAo + (ll)(z % p.zDiv) * p.sAi;
    ll offB = (ll)(z / p.zDiv) * p.sBo + (ll)(z % p.zDiv) * p.sBi;
    ll offC = (ll)(z / p.zDiv) * p.sCo + (ll)(z % p.zDiv) * p.sCi;
    const bf16* Ah = p.Ah + offA; const bf16* Al = p.Al + offA;
    const bf16* Bh = p.Bh + offB; const bf16* Bl = p.Bl + offB;

    int m0 = blockIdx.y * 128, n0 = blockIdx.x * 128;
    int tid = threadIdx.x, lane = tid & 31, wid = tid >> 5;
    int wm = (wid & 3) * 32, wn = (wid >> 2) * 64;
    u32 smu = (u32)__cvta_generic_to_shared(sm);

    float acc[2][8][4];
    #pragma unroll
    for (int a = 0; a < 2; a++)
        #pragma unroll
        for (int b = 0; b < 8; b++)
            #pragma unroll
            for (int c = 0; c < 4; c++) acc[a][b][c] = 0.f;

    int ldRow = tid >> 2;       // 0..63
    int ldC   = tid & 3;        // 16B chunk within 32 k-elems

    auto issue = [&](int c) {
        u32 base = smu + (u32)(c % NSTG) * STG_B;
        int k0 = c * KC;
        #pragma unroll
        for (int hh = 0; hh < 2; hh++) {
            int row = ldRow + hh * 64;
            u32 so = (u32)(row * PAD + ldC * 8) * 2;
            ll ao = (ll)(m0 + row) * p.lda + k0 + ldC * 8;
            ll bo = (ll)(n0 + row) * p.ldb + k0 + ldC * 8;
            cpa16(base + 0 * TILE_E * 2 + so, Ah + ao);
            cpa16(base + 1 * TILE_E * 2 + so, Al + ao);
            cpa16(base + 2 * TILE_E * 2 + so, Bh + bo);
            cpa16(base + 3 * TILE_E * 2 + so, Bl + bo);
        }
        asm volatile("cp.async.commit_group;" ::: "memory");
    };

    int nch = p.K / KC;
    issue(0);
    if (nch > 1) issue(1);

    for (int c = 0; c < nch; c++) {
        if (c + 1 < nch) asm volatile("cp.async.wait_group 1;" ::: "memory");
        else             asm volatile("cp.async.wait_group 0;" ::: "memory");
        __syncthreads();
        if (c + 2 < nch) issue(c + 2);

        u32 aB  = smu + (u32)(c % NSTG) * STG_B;
        u32 alB = aB + TILE_E * 2;
        u32 bB  = aB + 2 * TILE_E * 2;
        u32 blB = aB + 3 * TILE_E * 2;

        #pragma unroll
        for (int ks = 0; ks < 2; ks++) {
            u32 ah[2][4], al[2][4], bh[8][2], bl[8][2];
            #pragma unroll
            for (int mi = 0; mi < 2; mi++) {
                int row = wm + mi * 16 + (lane & 15);
                int col = ks * 16 + (lane >> 4) * 8;
                u32 off = (u32)(row * PAD + col) * 2;
                ldsm4(ah[mi], aB + off);
                ldsm4(al[mi], alB + off);
            }
            #pragma unroll
            for (int nj = 0; nj < 4; nj++) {
                int g = lane >> 3;
                int row = wn + nj * 16 + ((g >> 1) << 3) + (lane & 7);
                int col = ks * 16 + ((g & 1) << 3);
                u32 off = (u32)(row * PAD + col) * 2;
                u32 t[4];
                ldsm4(t, bB + off);
                bh[nj*2][0] = t[0]; bh[nj*2][1] = t[1];
                bh[nj*2+1][0] = t[2]; bh[nj*2+1][1] = t[3];
                ldsm4(t, blB + off);
                bl[nj*2][0] = t[0]; bl[nj*2][1] = t[1];
                bl[nj*2+1][0] = t[2]; bl[nj*2+1][1] = t[3];
            }
            #pragma unroll
            for (int mi = 0; mi < 2; mi++)
                #pragma unroll
                for (int nf = 0; nf < 8; nf++) {
                    mma_bf16(acc[mi][nf], ah[mi], bh[nf]);
                    mma_bf16(acc[mi][nf], ah[mi], bl[nf]);
                    mma_bf16(acc[mi][nf], al[mi], bh[nf]);
                }
        }
    }

    // ---- epilogue (register fragments; columns come in adjacent pairs) ----
    float* Cp = p.C ? p.C + offC : nullptr;
    bf16* Chp = p.Ch ? p.Ch + offC : nullptr;
    bf16* Clp = p.Cl ? p.Cl + offC : nullptr;
    #pragma unroll
    for (int mi = 0; mi < 2; mi++)
        #pragma unroll
        for (int nf = 0; nf < 8; nf++) {
            int rB = m0 + wm + mi * 16 + (lane >> 2);
            int cB = n0 + wn + nf * 8 + (lane & 3) * 2;
            #pragma unroll
            for (int pe = 0; pe < 2; pe++) {
                int m = rB + pe * 8;
                float v0 = acc[mi][nf][pe * 2 + 0];
                float v1 = acc[mi][nf][pe * 2 + 1];
                if (p.biasMode == 1) { v0 += p.bias[cB]; v1 += p.bias[cB + 1]; }
                else if (p.biasMode == 2) { float bb = p.bias[m]; v0 += bb; v1 += bb; }
                if (p.act == 1) { v0 = gelu_exact(v0); v1 = gelu_exact(v1); }
                else if (p.act == 2) {
                    int s = m & (S - 1);
                    int j = (cB & 127) >> 1;
                    float freq = powf(10000.f, -(float)(2 * j) * (1.f / 128.f));
                    float ang = (float)s * freq;
                    float cc, ss; sincosf(ang, &ss, &cc);
                    const float sc = 0.29730177875068026f;  // 128^-0.25
                    float r0 = (v0 * cc - v1 * ss) * sc;
                    float r1 = (v0 * ss + v1 * cc) * sc;
                    v0 = r0; v1 = r1;
                }
                ll off0, off1;
                if (p.transStore) { off0 = (ll)cB * p.ldc + m; off1 = (ll)(cB + 1) * p.ldc + m; }
                else              { off0 = (ll)m * p.ldc + cB; off1 = off0 + 1; }
                if (p.outF32) {
                    float w0 = v0, w1 = v1;
                    if (p.addC) { w0 += Cp[off0]; w1 += Cp[off1]; }
                    Cp[off0] = w0; Cp[off1] = w1;
                }
                if (p.outBf) {
                    bf16 h, l;
                    splitf(v0, h, l); Chp[off0] = h; Clp[off0] = l;
                    splitf(v1, h, l); Chp[off1] = h; Clp[off1] = l;
                }
            }
        }
}

// ---------------- weight split ----------------
__global__ void split_k(const float* __restrict__ in, bf16* __restrict__ hi,
                        bf16* __restrict__ lo, ll n) {
    ll i = ((ll)blockIdx.x * 256 + threadIdx.x) * 4;
    if (i >= n) return;
    float4 v = *(const float4*)&in[i];
    bf16 h, l;
    splitf(v.x, h, l); hi[i+0] = h; lo[i+0] = l;
    splitf(v.y, h, l); hi[i+1] = h; lo[i+1] = l;
    splitf(v.z, h, l); hi[i+2] = h; lo[i+2] = l;
    splitf(v.w, h, l); hi[i+3] = h; lo[i+3] = l;
}

// ---------------- im2col ----------------
__global__ void im2col1_k(const float* __restrict__ x) {
    int idx = blockIdx.x * 256 + threadIdx.x;
    const int total = Bn * T1 * 384;
    if (idx >= total) return;
    int r = idx % 384;
    int t = (idx / 384) % T1;
    int b = idx / (384 * T1);
    int i = r / 3, kk = r % 3;
    int pos = 2 * t + kk - 1;
    float v = (pos >= 0 && pos < TIN) ? x[((ll)b * NMELS + i) * TIN + pos] : 0.f;
    bf16 h, l; splitf(v, h, l);
    g_colh[idx] = h; g_coll[idx] = l;
}
__global__ void im2col2_k() {
    ll idx = (ll)blockIdx.x * 256 + threadIdx.x;
    const ll total = (ll)Bn * S * 3072;
    if (idx >= total) return;
    int r = (int)(idx % 3072);
    int t = (int)((idx / 3072) % S);
    int b = (int)(idx / ((ll)S * 3072));
    int i = r / 3, kk = r % 3;
    int pos = 2 * t + kk - 1;
    float v = (pos >= 0 && pos < T1) ? g_h1[((ll)b * T1 + pos) * D + i] : 0.f;
    bf16 h, l; splitf(v, h, l);
    g_colh[idx] = h; g_coll[idx] = l;
}

// ---------------- LayerNorm -> bf16 hi/lo ----------------
__global__ void ln_k(const float* __restrict__ x,
                     const float* __restrict__ w, const float* __restrict__ b) {
    int row = blockIdx.x;
    int tid = threadIdx.x;
    const float* xr = x + (ll)row * D;
    __shared__ float red[256];
    float v[4];
    #pragma unroll
    for (int i = 0; i < 4; i++) v[i] = xr[tid + 256 * i];
    float s = v[0] + v[1] + v[2] + v[3];
    red[tid] = s; __syncthreads();
    for (int o = 128; o > 0; o >>= 1) { if (tid < o) red[tid] += red[tid + o]; __syncthreads(); }
    float mean = red[0] * (1.f / D);
    __syncthreads();
    float sq = 0.f;
    #pragma unroll
    for (int i = 0; i < 4; i++) { float d0 = v[i] - mean; sq += d0 * d0; }
    red[tid] = sq; __syncthreads();
    for (int o = 128; o > 0; o >>= 1) { if (tid < o) red[tid] += red[tid + o]; __syncthreads(); }
    float rstd = rsqrtf(red[0] * (1.f / D) + 1e-5f);
    #pragma unroll
    for (int i = 0; i < 4; i++) {
        int c = tid + 256 * i;
        float y = (v[i] - mean) * rstd * w[c] + b[c];
        bf16 h, l; splitf(y, h, l);
        g_yh[(ll)row * D + c] = h; g_yl[(ll)row * D + c] = l;
    }
}

// ---------------- masked softmax -> bf16 hi/lo probs ----------------
__global__ void softmax_k(const int* __restrict__ x_len) {
    ll row = blockIdx.x;
    int b = (int)(row >> 13);
    const float* r = g_scores + row * S;
    int tid = threadIdx.x;
    int xl = x_len[b];
    __shared__ float red[256];
    float v[4];
    #pragma unroll
    for (int i = 0; i < 4; i++) {
        int j = tid + 256 * i;
        float bias = (4 * j + 3 < xl) ? 0.f : -1e10f;
        v[i] = r[j] + bias;
    }
    float m = fmaxf(fmaxf(v[0], v[1]), fmaxf(v[2], v[3]));
    red[tid] = m; __syncthreads();
    for (int o = 128; o > 0; o >>= 1) { if (tid < o) red[tid] = fmaxf(red[tid], red[tid + o]); __syncthreads(); }
    m = red[0]; __syncthreads();
    float s = 0.f;
    #pragma unroll
    for (int i = 0; i < 4; i++) { v[i] = expf(v[i] - m); s += v[i]; }
    red[tid] = s; __syncthreads();
    for (int o = 128; o > 0; o >>= 1) { if (tid < o) red[tid] += red[tid + o]; __syncthreads(); }
    float inv = 1.f / red[0];
    #pragma unroll
    for (int i = 0; i < 4; i++) {
        float pv = v[i] * inv;
        bf16 h, l; splitf(pv, h, l);
        g_ph[row * S + tid + 256 * i] = h;
        g_pl[row * S + tid + 256 * i] = l;
    }
}

// ---------------- output ----------------
__global__ void out_k(float* __restrict__ out, const int* __restrict__ x_len, ll out_size) {
    ll i = (ll)blockIdx.x * 256 + threadIdx.x;
    const ll nh = (ll)NTOK * D;
    if (i < nh && i < out_size) out[i] = g_x[i];
    if (i < Bn) {
        ll pos = nh + i;
        if (pos < out_size) {
            int yl = (x_len[i] + 1) / 2;
            yl = (yl + 1) / 2;
            out[pos] = (float)yl;
        }
    }
}

// ---------------- host launcher ----------------
extern "C" void kernel_launch(void* const* d_in, const int* in_sizes, int n_in,
                              void* d_out, int out_size) {
    const float* x        = (const float*)d_in[0];
    const int*   x_len    = (const int*)  d_in[1];
    const float* conv1_w  = (const float*)d_in[2];
    const float* conv1_b  = (const float*)d_in[3];
    const float* conv2_w  = (const float*)d_in[4];
    const float* conv2_b  = (const float*)d_in[5];
    const float* attn_ln_w= (const float*)d_in[6];
    const float* attn_ln_b= (const float*)d_in[7];
    const float* q_w      = (const float*)d_in[8];
    const float* q_b      = (const float*)d_in[9];
    const float* k_w      = (const float*)d_in[10];
    const float* v_w      = (const float*)d_in[11];
    const float* v_b      = (const float*)d_in[12];
    const float* out_w    = (const float*)d_in[13];
    const float* out_b    = (const float*)d_in[14];
    const float* mlp_ln_w = (const float*)d_in[15];
    const float* mlp_ln_b = (const float*)d_in[16];
    const float* mlp1_w   = (const float*)d_in[17];
    const float* mlp1_b   = (const float*)d_in[18];
    const float* mlp2_w   = (const float*)d_in[19];
    const float* mlp2_b   = (const float*)d_in[20];

    cudaFuncSetAttribute(gemm_tc, cudaFuncAttributeMaxDynamicSharedMemorySize, SMEM_TOT);

    #define SYM(p, s) do { void* _t; cudaGetSymbolAddress(&_t, s); p = (decltype(p))_t; } while (0)
    float *h1, *xs, *sc;
    SYM(h1, g_h1); SYM(xs, g_x); SYM(sc, g_scores);
    bf16 *pc1h,*pc1l,*pc2h,*pc2l,*pwqh,*pwql,*pwkh,*pwkl,*pwvh,*pwvl,*pwoh,*pwol;
    bf16 *pw1h,*pw1l,*pw2h,*pw2l,*pcolh,*pcoll,*pyh,*pyl,*pqh,*pql,*pkh,*pkl;
    bf16 *pvth,*pvtl,*pph,*ppl,*pm1h,*pm1l,*poh,*pol;
    SYM(pc1h, c1h); SYM(pc1l, c1l); SYM(pc2h, c2h); SYM(pc2l, c2l);
    SYM(pwqh, wqh); SYM(pwql, wql); SYM(pwkh, wkh); SYM(pwkl, wkl);
    SYM(pwvh, wvh); SYM(pwvl, wvl); SYM(pwoh, woh); SYM(pwol, wol);
    SYM(pw1h, w1h); SYM(pw1l, w1l); SYM(pw2h, w2h); SYM(pw2l, w2l);
    SYM(pcolh, g_colh); SYM(pcoll, g_coll); SYM(pyh, g_yh); SYM(pyl, g_yl);
    SYM(pqh, g_qh); SYM(pql, g_ql); SYM(pkh, g_kh); SYM(pkl, g_kl);
    SYM(pvth, g_vth); SYM(pvtl, g_vtl); SYM(pph, g_ph); SYM(ppl, g_pl);
    SYM(pm1h, g_m1h); SYM(pm1l, g_m1l); SYM(poh, g_oh); SYM(pol, g_ol);

    auto split = [&](const float* in, bf16* hi, bf16* lo, ll n) {
        split_k<<<(int)((n / 4 + 255) / 256), 256>>>(in, hi, lo, n);
    };
    split(conv1_w, pc1h, pc1l, (ll)D * 384);
    split(conv2_w, pc2h, pc2l, (ll)D * 3072);
    split(q_w,   pwqh, pwql, (ll)Ldim * D * D);
    split(k_w,   pwkh, pwkl, (ll)Ldim * D * D);
    split(v_w,   pwvh, pwvl, (ll)Ldim * D * D);
    split(out_w, pwoh, pwol, (ll)Ldim * D * D);
    split(mlp1_w, pw1h, pw1l, (ll)Ldim * Fdim * D);
    split(mlp2_w, pw2h, pw2l, (ll)Ldim * Fdim * D);

    auto gemm = [&](const bf16* Ah, const bf16* Al, const bf16* Bh, const bf16* Bl,
                    float* C, bf16* Ch, bf16* Cl, const float* bias,
                    int M, int N, int K, int lda, int ldb, int ldc,
                    int nz, int zDiv,
                    ll sAo, ll sAi, ll sBo, ll sBi, ll sCo, ll sCi,
                    int biasMode, int addC, int act, int transStore,
                    int outF32, int outBf) {
        GemmP p;
        p.Ah = Ah; p.Al = Al; p.Bh = Bh; p.Bl = Bl;
        p.C = C; p.Ch = Ch; p.Cl = Cl; p.bias = bias;
        p.K = K; p.lda = lda; p.ldb = ldb; p.ldc = ldc;
        p.zDiv = zDiv;
        p.sAo = sAo; p.sAi = sAi; p.sBo = sBo; p.sBi = sBi; p.sCo = sCo; p.sCi = sCi;
        p.biasMode = biasMode; p.addC = addC; p.act = act;
        p.transStore = transStore; p.outF32 = outF32; p.outBf = outBf;
        dim3 g(N / 128, M / 128, nz);
        gemm_tc<<<g, 256, SMEM_TOT>>>(p);
    };

    const ll SD = (ll)S * D;
    const ll SS = (ll)S * S;

    // conv1: A = im2col [b][t][384] (M=T1), B = W1 [D][384], C = g_h1 [b][t][d]
    im2col1_k<<<(Bn * T1 * 384 + 255) / 256, 256>>>(x);
    gemm(pcolh, pcoll, pc1h, pc1l, h1, 0, 0, conv1_b,
         T1, 1024, 384, 384, 384, D,
         Bn, 1, (ll)T1 * 384, 0, 0, 0, (ll)T1 * D, 0,
         1, 0, 1, 0, 1, 0);

    // conv2: A = im2col [b][t][3072] (M=S), B = W2 [D][3072], C = g_x [tok][d]
    im2col2_k<<<(int)(((ll)Bn * S * 3072 + 255) / 256), 256>>>();
    gemm(pcolh, pcoll, pc2h, pc2l, xs, 0, 0, conv2_b,
         S, 1024, 3072, 3072, 3072, D,
         Bn, 1, (ll)S * 3072, 0, 0, 0, SD, 0,
         1, 0, 1, 0, 1, 0);

    for (int l = 0; l < 6; l++) {
        const float* aw = attn_ln_w + l * D;  const float* ab = attn_ln_b + l * D;
        const float* qb = q_b + l * D;
        const float* vb = v_b + l * D;
        const float* ob = out_b + l * D;
        const float* mw = mlp_ln_w + l * D;   const float* mb2 = mlp_ln_b + l * D;
        const float* b1 = mlp1_b + l * Fdim;
        const float* b2 = mlp2_b + l * D;
        ll wOff = (ll)l * D * D;
        ll mOff = (ll)l * Fdim * D;

        ln_k<<<NTOK, 256>>>(xs, aw, ab);

        // q, k with fused RoPE+scale epilogue -> bf16 hi/lo; v -> bf16 transposed [d][tok]
        gemm(pyh, pyl, pwqh + wOff, pwql + wOff, 0, pqh, pql, qb,
             NTOK, D, D, D, D, D, 1, 1, 0,0,0,0,0,0, 1, 0, 2, 0, 0, 1);
        gemm(pyh, pyl, pwkh + wOff, pwkl + wOff, 0, pkh, pkl, 0,
             NTOK, D, D, D, D, D, 1, 1, 0,0,0,0,0,0, 0, 0, 2, 0, 0, 1);
        gemm(pyh, pyl, pwvh + wOff, pwvl + wOff, 0, pvth, pvtl, vb,
             NTOK, D, D, D, D, NTOK, 1, 1, 0,0,0,0,0,0, 1, 0, 0, 1, 0, 1);

        // scores[b,h] = q_bh [S,128] @ k_bh^T
        gemm(pqh, pql, pkh, pkl, sc, 0, 0, 0,
             S, S, DH, D, D, S,
             Bn * H, H, SD, 128, SD, 128, (ll)H * SS, SS,
             0, 0, 0, 0, 1, 0);

        softmax_k<<<Bn * H * S, 256>>>(x_len);

        // o[b,h] = probs [S,S] @ vT_bh^T
        gemm(pph, ppl, pvth, pvtl, 0, poh, pol, 0,
             S, DH, S, S, NTOK, D,
             Bn * H, H, (ll)H * SS, SS, S, (ll)128 * NTOK, SD, 128,
             0, 0, 0, 0, 0, 1);

        // out projection + residual
        gemm(poh, pol, pwoh + wOff, pwol + wOff, xs, 0, 0, ob,
             NTOK, D, D, D, D, D, 1, 1, 0,0,0,0,0,0, 1, 1, 0, 0, 1, 0);

        // MLP
        ln_k<<<NTOK, 256>>>(xs, mw, mb2);
        gemm(pyh, pyl, pw1h + mOff, pw1l + mOff, 0, pm1h, pm1l, b1,
             NTOK, Fdim, D, D, D, Fdim, 1, 1, 0,0,0,0,0,0, 1, 0, 1, 0, 0, 1);
        gemm(pm1h, pm1l, pw2h + mOff, pw2l + mOff, xs, 0, 0, b2,
             NTOK, D, Fdim, Fdim, Fdim, D, 1, 1, 0,0,0,0,0,0, 1, 1, 0, 0, 1, 0);
    }

    ll nh = (ll)NTOK * D;
    out_k<<<(int)((nh + 255) / 256), 256>>>((float*)d_out, x_len, (ll)out_size);
}

// round 5
// speedup vs baseline: 1.1406x; 1.1406x over previous
#include <cuda_runtime.h>
#include <cuda_bf16.h>
#include <math.h>

typedef __nv_bfloat16 bf16;
typedef long long ll;
typedef unsigned u32;

#define Bn 8
#define NMELS 128
#define TIN 4096
#define T1 2048
#define S 1024
#define D 1024
#define H 8
#define DH 128
#define Fdim 4096
#define NTOK (Bn*S)
#define Ldim 6

// ---------------- fp32 scratch ----------------
__device__ float g_h1[(size_t)Bn*T1*D];            // conv1 out [b][t][d]
__device__ float g_x [(size_t)NTOK*D];             // residual stream
__device__ float g_scores[(size_t)Bn*H*S*S];

// ---------------- bf16 hi/lo buffers ----------------
__device__ __align__(256) bf16 c1h[(size_t)D*384],  c1l[(size_t)D*384];
__device__ __align__(256) bf16 c2h[(size_t)D*3072], c2l[(size_t)D*3072];
__device__ __align__(256) bf16 wqh[(size_t)Ldim*D*D], wql[(size_t)Ldim*D*D];
__device__ __align__(256) bf16 wkh[(size_t)Ldim*D*D], wkl[(size_t)Ldim*D*D];
__device__ __align__(256) bf16 wvh[(size_t)Ldim*D*D], wvl[(size_t)Ldim*D*D];
__device__ __align__(256) bf16 woh[(size_t)Ldim*D*D], wol[(size_t)Ldim*D*D];
__device__ __align__(256) bf16 w1h[(size_t)Ldim*Fdim*D], w1l[(size_t)Ldim*Fdim*D];
__device__ __align__(256) bf16 w2h[(size_t)Ldim*Fdim*D], w2l[(size_t)Ldim*Fdim*D];
__device__ __align__(256) bf16 g_colh[(size_t)Bn*3072*S], g_coll[(size_t)Bn*3072*S];
__device__ __align__(256) bf16 g_yh[(size_t)NTOK*D], g_yl[(size_t)NTOK*D];
__device__ __align__(256) bf16 g_qh[(size_t)NTOK*D], g_ql[(size_t)NTOK*D];
__device__ __align__(256) bf16 g_kh[(size_t)NTOK*D], g_kl[(size_t)NTOK*D];
__device__ __align__(256) bf16 g_vth[(size_t)D*NTOK], g_vtl[(size_t)D*NTOK];
__device__ __align__(256) bf16 g_ph[(size_t)Bn*H*S*S], g_pl[(size_t)Bn*H*S*S];
__device__ __align__(256) bf16 g_m1h[(size_t)NTOK*Fdim], g_m1l[(size_t)NTOK*Fdim];
__device__ __align__(256) bf16 g_oh[(size_t)NTOK*D], g_ol[(size_t)NTOK*D];

// ---------------- helpers ----------------
__device__ __forceinline__ float gelu_exact(float v) {
    return 0.5f * v * (1.0f + erff(v * 0.70710678118654752f));
}
__device__ __forceinline__ void splitf(float v, bf16& h, bf16& l) {
    h = __float2bfloat16_rn(v);
    l = __float2bfloat16_rn(v - __bfloat162float(h));
}
__device__ __forceinline__ void mma_bf16(float* d, const u32* a, const u32* b) {
    asm volatile(
        "mma.sync.aligned.m16n8k16.row.col.f32.bf16.bf16.f32 "
        "{%0,%1,%2,%3}, {%4,%5,%6,%7}, {%8,%9}, {%0,%1,%2,%3};\n"
        : "+f"(d[0]), "+f"(d[1]), "+f"(d[2]), "+f"(d[3])
        : "r"(a[0]), "r"(a[1]), "r"(a[2]), "r"(a[3]), "r"(b[0]), "r"(b[1]));
}
__device__ __forceinline__ void ldsm4(u32* r, u32 addr) {
    asm volatile("ldmatrix.sync.aligned.m8n8.x4.shared.b16 {%0,%1,%2,%3}, [%4];\n"
        : "=r"(r[0]), "=r"(r[1]), "=r"(r[2]), "=r"(r[3]) : "r"(addr));
}
__device__ __forceinline__ void cpa16(u32 dst, const void* src) {
    asm volatile("cp.async.cg.shared.global [%0], [%1], 16;\n" :: "r"(dst), "l"(src));
}

// ---------------- bf16x3 tensor-core GEMM (mma.sync, 16 warps, 3-stage) ----------------
// C[M,N] = A[M,K] * B[N,K]^T
#define KC 32
#define NSTG 3
#define PAD 40
#define TILE_E (128*PAD)             // bf16 elems per smem operand tile
#define STG_B  (4*TILE_E*2)          // bytes per stage (Ah,Al,Bh,Bl) = 40960
#define SMEM_TOT (NSTG*STG_B)        // 122880

struct GemmP {
    const bf16 *Ah, *Al, *Bh, *Bl;
    float* C; bf16 *Ch, *Cl;
    const float* bias;
    int K, lda, ldb, ldc;
    int zDiv;
    ll sAo, sAi, sBo, sBi, sCo, sCi;
    int biasMode;   // 0 none, 1 per-col(n), 2 per-row(m)
    int addC;       // fp32 residual accumulate
    int act;        // 0 none, 1 exact GELU, 2 RoPE+scale (pairs of columns)
    int transStore; // store (m,n) at [n*ldc+m]
    int outF32, outBf;
};

__global__ __launch_bounds__(512, 1) void gemm_tc(GemmP p) {
    extern __shared__ __align__(16) bf16 sm[];
    int z = blockIdx.z;
    ll offA = (ll)(z / p.zDiv) * p.sAo + (ll)(z % p.zDiv) * p.sAi;
    ll offB = (ll)(z / p.zDiv) * p.sBo + (ll)(z % p.zDiv) * p.sBi;
    ll offC = (ll)(z / p.zDiv) * p.sCo + (ll)(z % p.zDiv) * p.sCi;
    const bf16* Ah = p.Ah + offA; const bf16* Al = p.Al + offA;
    const bf16* Bh = p.Bh + offB; const bf16* Bl = p.Bl + offB;

    int m0 = blockIdx.y * 128, n0 = blockIdx.x * 128;
    int tid = threadIdx.x, lane = tid & 31, wid = tid >> 5;
    int wm = (wid & 3) * 32, wn = (wid >> 2) * 32;
    u32 smu = (u32)__cvta_generic_to_shared(sm);

    float acc[2][4][4];
    #pragma unroll
    for (int a = 0; a < 2; a++)
        #pragma unroll
        for (int b = 0; b < 4; b++)
            #pragma unroll
            for (int c = 0; c < 4; c++) acc[a][b][c] = 0.f;

    int ldRow = tid >> 2;       // 0..127
    int ldC   = tid & 3;        // 16B chunk within 32 k-elems

    auto issue = [&](int c) {
        u32 base = smu + (u32)(c % NSTG) * STG_B;
        int k0 = c * KC;
        u32 so = (u32)(ldRow * PAD + ldC * 8) * 2;
        ll ao = (ll)(m0 + ldRow) * p.lda + k0 + ldC * 8;
        ll bo = (ll)(n0 + ldRow) * p.ldb + k0 + ldC * 8;
        cpa16(base + 0 * TILE_E * 2 + so, Ah + ao);
        cpa16(base + 1 * TILE_E * 2 + so, Al + ao);
        cpa16(base + 2 * TILE_E * 2 + so, Bh + bo);
        cpa16(base + 3 * TILE_E * 2 + so, Bl + bo);
        asm volatile("cp.async.commit_group;" ::: "memory");
    };

    int nch = p.K / KC;
    issue(0);
    if (nch > 1) issue(1);

    for (int c = 0; c < nch; c++) {
        if (c + 1 < nch) asm volatile("cp.async.wait_group 1;" ::: "memory");
        else             asm volatile("cp.async.wait_group 0;" ::: "memory");
        __syncthreads();
        if (c + 2 < nch) issue(c + 2);

        u32 aB  = smu + (u32)(c % NSTG) * STG_B;
        u32 alB = aB + TILE_E * 2;
        u32 bB  = aB + 2 * TILE_E * 2;
        u32 blB = aB + 3 * TILE_E * 2;

        #pragma unroll
        for (int ks = 0; ks < 2; ks++) {
            u32 ah[2][4], al[2][4], bh[4][2], bl[4][2];
            #pragma unroll
            for (int mi = 0; mi < 2; mi++) {
                int row = wm + mi * 16 + (lane & 15);
                int col = ks * 16 + (lane >> 4) * 8;
                u32 off = (u32)(row * PAD + col) * 2;
                ldsm4(ah[mi], aB + off);
                ldsm4(al[mi], alB + off);
            }
            #pragma unroll
            for (int nj = 0; nj < 2; nj++) {
                int g = lane >> 3;
                int row = wn + nj * 16 + ((g >> 1) << 3) + (lane & 7);
                int col = ks * 16 + ((g & 1) << 3);
                u32 off = (u32)(row * PAD + col) * 2;
                u32 t[4];
                ldsm4(t, bB + off);
                bh[nj*2][0] = t[0]; bh[nj*2][1] = t[1];
                bh[nj*2+1][0] = t[2]; bh[nj*2+1][1] = t[3];
                ldsm4(t, blB + off);
                bl[nj*2][0] = t[0]; bl[nj*2][1] = t[1];
                bl[nj*2+1][0] = t[2]; bl[nj*2+1][1] = t[3];
            }
            #pragma unroll
            for (int mi = 0; mi < 2; mi++)
                #pragma unroll
                for (int nf = 0; nf < 4; nf++)
                    mma_bf16(acc[mi][nf], ah[mi], bh[nf]);
            #pragma unroll
            for (int mi = 0; mi < 2; mi++)
                #pragma unroll
                for (int nf = 0; nf < 4; nf++)
                    mma_bf16(acc[mi][nf], ah[mi], bl[nf]);
            #pragma unroll
            for (int mi = 0; mi < 2; mi++)
                #pragma unroll
                for (int nf = 0; nf < 4; nf++)
                    mma_bf16(acc[mi][nf], al[mi], bh[nf]);
        }
    }

    // ---- epilogue (register fragments; columns come in adjacent pairs) ----
    float* Cp = p.C ? p.C + offC : nullptr;
    bf16* Chp = p.Ch ? p.Ch + offC : nullptr;
    bf16* Clp = p.Cl ? p.Cl + offC : nullptr;
    #pragma unroll
    for (int mi = 0; mi < 2; mi++)
        #pragma unroll
        for (int nf = 0; nf < 4; nf++) {
            int rB = m0 + wm + mi * 16 + (lane >> 2);
            int cB = n0 + wn + nf * 8 + (lane & 3) * 2;
            #pragma unroll
            for (int pe = 0; pe < 2; pe++) {
                int m = rB + pe * 8;
                float v0 = acc[mi][nf][pe * 2 + 0];
                float v1 = acc[mi][nf][pe * 2 + 1];
                if (p.biasMode == 1) { v0 += p.bias[cB]; v1 += p.bias[cB + 1]; }
                else if (p.biasMode == 2) { float bb = p.bias[m]; v0 += bb; v1 += bb; }
                if (p.act == 1) { v0 = gelu_exact(v0); v1 = gelu_exact(v1); }
                else if (p.act == 2) {
                    int s = m & (S - 1);
                    int j = (cB & 127) >> 1;
                    float freq = powf(10000.f, -(float)(2 * j) * (1.f / 128.f));
                    float ang = (float)s * freq;
                    float cc, ss; sincosf(ang, &ss, &cc);
                    const float sc = 0.29730177875068026f;  // 128^-0.25
                    float r0 = (v0 * cc - v1 * ss) * sc;
                    float r1 = (v0 * ss + v1 * cc) * sc;
                    v0 = r0; v1 = r1;
                }
                if (!p.transStore) {
                    ll off0 = (ll)m * p.ldc + cB;
                    if (p.outF32) {
                        float w0 = v0, w1 = v1;
                        if (p.addC) {
                            float2 o = *(float2*)&Cp[off0];
                            w0 += o.x; w1 += o.y;
                        }
                        *(float2*)&Cp[off0] = make_float2(w0, w1);
                    }
                    if (p.outBf) {
                        bf16 h0, l0, h1, l1;
                        splitf(v0, h0, l0); splitf(v1, h1, l1);
                        u32 hp = (u32)__bfloat16_as_ushort(h0) | ((u32)__bfloat16_as_ushort(h1) << 16);
                        u32 lp = (u32)__bfloat16_as_ushort(l0) | ((u32)__bfloat16_as_ushort(l1) << 16);
                        *(u32*)&Chp[off0] = hp;
                        *(u32*)&Clp[off0] = lp;
                    }
                } else {
                    ll off0 = (ll)cB * p.ldc + m;
                    ll off1 = off0 + p.ldc;
                    if (p.outF32) {
                        float w0 = v0, w1 = v1;
                        if (p.addC) { w0 += Cp[off0]; w1 += Cp[off1]; }
                        Cp[off0] = w0; Cp[off1] = w1;
                    }
                    if (p.outBf) {
                        bf16 h, l;
                        splitf(v0, h, l); Chp[off0] = h; Clp[off0] = l;
                        splitf(v1, h, l); Chp[off1] = h; Clp[off1] = l;
                    }
                }
            }
        }
}

// ---------------- weight split ----------------
__global__ void split_k(const float* __restrict__ in, bf16* __restrict__ hi,
                        bf16* __restrict__ lo, ll n) {
    ll i = ((ll)blockIdx.x * 256 + threadIdx.x) * 4;
    if (i >= n) return;
    float4 v = *(const float4*)&in[i];
    bf16 h, l;
    splitf(v.x, h, l); hi[i+0] = h; lo[i+0] = l;
    splitf(v.y, h, l); hi[i+1] = h; lo[i+1] = l;
    splitf(v.z, h, l); hi[i+2] = h; lo[i+2] = l;
    splitf(v.w, h, l); hi[i+3] = h; lo[i+3] = l;
}

// ---------------- im2col ----------------
__global__ void im2col1_k(const float* __restrict__ x) {
    int idx = blockIdx.x * 256 + threadIdx.x;
    const int total = Bn * T1 * 384;
    if (idx >= total) return;
    int r = idx % 384;
    int t = (idx / 384) % T1;
    int b = idx / (384 * T1);
    int i = r / 3, kk = r % 3;
    int pos = 2 * t + kk - 1;
    float v = (pos >= 0 && pos < TIN) ? x[((ll)b * NMELS + i) * TIN + pos] : 0.f;
    bf16 h, l; splitf(v, h, l);
    g_colh[idx] = h; g_coll[idx] = l;
}
__global__ void im2col2_k() {
    ll idx = (ll)blockIdx.x * 256 + threadIdx.x;
    const ll total = (ll)Bn * S * 3072;
    if (idx >= total) return;
    int r = (int)(idx % 3072);
    int t = (int)((idx / 3072) % S);
    int b = (int)(idx / ((ll)S * 3072));
    int i = r / 3, kk = r % 3;
    int pos = 2 * t + kk - 1;
    float v = (pos >= 0 && pos < T1) ? g_h1[((ll)b * T1 + pos) * D + i] : 0.f;
    bf16 h, l; splitf(v, h, l);
    g_colh[idx] = h; g_coll[idx] = l;
}

// ---------------- LayerNorm -> bf16 hi/lo ----------------
__global__ void ln_k(const float* __restrict__ x,
                     const float* __restrict__ w, const float* __restrict__ b) {
    int row = blockIdx.x;
    int tid = threadIdx.x;
    const float* xr = x + (ll)row * D;
    __shared__ float red[256];
    float v[4];
    #pragma unroll
    for (int i = 0; i < 4; i++) v[i] = xr[tid + 256 * i];
    float s = v[0] + v[1] + v[2] + v[3];
    red[tid] = s; __syncthreads();
    for (int o = 128; o > 0; o >>= 1) { if (tid < o) red[tid] += red[tid + o]; __syncthreads(); }
    float mean = red[0] * (1.f / D);
    __syncthreads();
    float sq = 0.f;
    #pragma unroll
    for (int i = 0; i < 4; i++) { float d0 = v[i] - mean; sq += d0 * d0; }
    red[tid] = sq; __syncthreads();
    for (int o = 128; o > 0; o >>= 1) { if (tid < o) red[tid] += red[tid + o]; __syncthreads(); }
    float rstd = rsqrtf(red[0] * (1.f / D) + 1e-5f);
    #pragma unroll
    for (int i = 0; i < 4; i++) {
        int c = tid + 256 * i;
        float y = (v[i] - mean) * rstd * w[c] + b[c];
        bf16 h, l; splitf(y, h, l);
        g_yh[(ll)row * D + c] = h; g_yl[(ll)row * D + c] = l;
    }
}

// ---------------- masked softmax -> bf16 hi/lo probs ----------------
__global__ void softmax_k(const int* __restrict__ x_len) {
    ll row = blockIdx.x;
    int b = (int)(row >> 13);
    const float* r = g_scores + row * S;
    int tid = threadIdx.x;
    int xl = x_len[b];
    __shared__ float red[256];
    float v[4];
    #pragma unroll
    for (int i = 0; i < 4; i++) {
        int j = tid + 256 * i;
        float bias = (4 * j + 3 < xl) ? 0.f : -1e10f;
        v[i] = r[j] + bias;
    }
    float m = fmaxf(fmaxf(v[0], v[1]), fmaxf(v[2], v[3]));
    red[tid] = m; __syncthreads();
    for (int o = 128; o > 0; o >>= 1) { if (tid < o) red[tid] = fmaxf(red[tid], red[tid + o]); __syncthreads(); }
    m = red[0]; __syncthreads();
    float s = 0.f;
    #pragma unroll
    for (int i = 0; i < 4; i++) { v[i] = expf(v[i] - m); s += v[i]; }
    red[tid] = s; __syncthreads();
    for (int o = 128; o > 0; o >>= 1) { if (tid < o) red[tid] += red[tid + o]; __syncthreads(); }
    float inv = 1.f / red[0];
    #pragma unroll
    for (int i = 0; i < 4; i++) {
        float pv = v[i] * inv;
        bf16 h, l; splitf(pv, h, l);
        g_ph[row * S + tid + 256 * i] = h;
        g_pl[row * S + tid + 256 * i] = l;
    }
}

// ---------------- output ----------------
__global__ void out_k(float* __restrict__ out, const int* __restrict__ x_len, ll out_size) {
    ll i = (ll)blockIdx.x * 256 + threadIdx.x;
    const ll nh = (ll)NTOK * D;
    if (i < nh && i < out_size) out[i] = g_x[i];
    if (i < Bn) {
        ll pos = nh + i;
        if (pos < out_size) {
            int yl = (x_len[i] + 1) / 2;
            yl = (yl + 1) / 2;
            out[pos] = (float)yl;
        }
    }
}

// ---------------- host launcher ----------------
extern "C" void kernel_launch(void* const* d_in, const int* in_sizes, int n_in,
                              void* d_out, int out_size) {
    const float* x        = (const float*)d_in[0];
    const int*   x_len    = (const int*)  d_in[1];
    const float* conv1_w  = (const float*)d_in[2];
    const float* conv1_b  = (const float*)d_in[3];
    const float* conv2_w  = (const float*)d_in[4];
    const float* conv2_b  = (const float*)d_in[5];
    const float* attn_ln_w= (const float*)d_in[6];
    const float* attn_ln_b= (const float*)d_in[7];
    const float* q_w      = (const float*)d_in[8];
    const float* q_b      = (const float*)d_in[9];
    const float* k_w      = (const float*)d_in[10];
    const float* v_w      = (const float*)d_in[11];
    const float* v_b      = (const float*)d_in[12];
    const float* out_w    = (const float*)d_in[13];
    const float* out_b    = (const float*)d_in[14];
    const float* mlp_ln_w = (const float*)d_in[15];
    const float* mlp_ln_b = (const float*)d_in[16];
    const float* mlp1_w   = (const float*)d_in[17];
    const float* mlp1_b   = (const float*)d_in[18];
    const float* mlp2_w   = (const float*)d_in[19];
    const float* mlp2_b   = (const float*)d_in[20];

    cudaFuncSetAttribute(gemm_tc, cudaFuncAttributeMaxDynamicSharedMemorySize, SMEM_TOT);

    #define SYM(p, s) do { void* _t; cudaGetSymbolAddress(&_t, s); p = (decltype(p))_t; } while (0)
    float *h1, *xs, *sc;
    SYM(h1, g_h1); SYM(xs, g_x); SYM(sc, g_scores);
    bf16 *pc1h,*pc1l,*pc2h,*pc2l,*pwqh,*pwql,*pwkh,*pwkl,*pwvh,*pwvl,*pwoh,*pwol;
    bf16 *pw1h,*pw1l,*pw2h,*pw2l,*pcolh,*pcoll,*pyh,*pyl,*pqh,*pql,*pkh,*pkl;
    bf16 *pvth,*pvtl,*pph,*ppl,*pm1h,*pm1l,*poh,*pol;
    SYM(pc1h, c1h); SYM(pc1l, c1l); SYM(pc2h, c2h); SYM(pc2l, c2l);
    SYM(pwqh, wqh); SYM(pwql, wql); SYM(pwkh, wkh); SYM(pwkl, wkl);
    SYM(pwvh, wvh); SYM(pwvl, wvl); SYM(pwoh, woh); SYM(pwol, wol);
    SYM(pw1h, w1h); SYM(pw1l, w1l); SYM(pw2h, w2h); SYM(pw2l, w2l);
    SYM(pcolh, g_colh); SYM(pcoll, g_coll); SYM(pyh, g_yh); SYM(pyl, g_yl);
    SYM(pqh, g_qh); SYM(pql, g_ql); SYM(pkh, g_kh); SYM(pkl, g_kl);
    SYM(pvth, g_vth); SYM(pvtl, g_vtl); SYM(pph, g_ph); SYM(ppl, g_pl);
    SYM(pm1h, g_m1h); SYM(pm1l, g_m1l); SYM(poh, g_oh); SYM(pol, g_ol);

    auto split = [&](const float* in, bf16* hi, bf16* lo, ll n) {
        split_k<<<(int)((n / 4 + 255) / 256), 256>>>(in, hi, lo, n);
    };
    split(conv1_w, pc1h, pc1l, (ll)D * 384);
    split(conv2_w, pc2h, pc2l, (ll)D * 3072);
    split(q_w,   pwqh, pwql, (ll)Ldim * D * D);
    split(k_w,   pwkh, pwkl, (ll)Ldim * D * D);
    split(v_w,   pwvh, pwvl, (ll)Ldim * D * D);
    split(out_w, pwoh, pwol, (ll)Ldim * D * D);
    split(mlp1_w, pw1h, pw1l, (ll)Ldim * Fdim * D);
    split(mlp2_w, pw2h, pw2l, (ll)Ldim * Fdim * D);

    auto gemm = [&](const bf16* Ah, const bf16* Al, const bf16* Bh, const bf16* Bl,
                    float* C, bf16* Ch, bf16* Cl, const float* bias,
                    int M, int N, int K, int lda, int ldb, int ldc,
                    int nz, int zDiv,
                    ll sAo, ll sAi, ll sBo, ll sBi, ll sCo, ll sCi,
                    int biasMode, int addC, int act, int transStore,
                    int outF32, int outBf) {
        GemmP p;
        p.Ah = Ah; p.Al = Al; p.Bh = Bh; p.Bl = Bl;
        p.C = C; p.Ch = Ch; p.Cl = Cl; p.bias = bias;
        p.K = K; p.lda = lda; p.ldb = ldb; p.ldc = ldc;
        p.zDiv = zDiv;
        p.sAo = sAo; p.sAi = sAi; p.sBo = sBo; p.sBi = sBi; p.sCo = sCo; p.sCi = sCi;
        p.biasMode = biasMode; p.addC = addC; p.act = act;
        p.transStore = transStore; p.outF32 = outF32; p.outBf = outBf;
        dim3 g(N / 128, M / 128, nz);
        gemm_tc<<<g, 512, SMEM_TOT>>>(p);
    };

    const ll SD = (ll)S * D;
    const ll SS = (ll)S * S;

    // conv1: A = im2col [b][t][384] (M=T1), B = W1 [D][384], C = g_h1 [b][t][d]
    im2col1_k<<<(Bn * T1 * 384 + 255) / 256, 256>>>(x);
    gemm(pcolh, pcoll, pc1h, pc1l, h1, 0, 0, conv1_b,
         T1, 1024, 384, 384, 384, D,
         Bn, 1, (ll)T1 * 384, 0, 0, 0, (ll)T1 * D, 0,
         1, 0, 1, 0, 1, 0);

    // conv2: A = im2col [b][t][3072] (M=S), B = W2 [D][3072], C = g_x [tok][d]
    im2col2_k<<<(int)(((ll)Bn * S * 3072 + 255) / 256), 256>>>();
    gemm(pcolh, pcoll, pc2h, pc2l, xs, 0, 0, conv2_b,
         S, 1024, 3072, 3072, 3072, D,
         Bn, 1, (ll)S * 3072, 0, 0, 0, SD, 0,
         1, 0, 1, 0, 1, 0);

    for (int l = 0; l < 6; l++) {
        const float* aw = attn_ln_w + l * D;  const float* ab = attn_ln_b + l * D;
        const float* qb = q_b + l * D;
        const float* vb = v_b + l * D;
        const float* ob = out_b + l * D;
        const float* mw = mlp_ln_w + l * D;   const float* mb2 = mlp_ln_b + l * D;
        const float* b1 = mlp1_b + l * Fdim;
        const float* b2 = mlp2_b + l * D;
        ll wOff = (ll)l * D * D;
        ll mOff = (ll)l * Fdim * D;

        ln_k<<<NTOK, 256>>>(xs, aw, ab);

        // q, k with fused RoPE+scale epilogue -> bf16 hi/lo; v -> bf16 transposed [d][tok]
        gemm(pyh, pyl, pwqh + wOff, pwql + wOff, 0, pqh, pql, qb,
             NTOK, D, D, D, D, D, 1, 1, 0,0,0,0,0,0, 1, 0, 2, 0, 0, 1);
        gemm(pyh, pyl, pwkh + wOff, pwkl + wOff, 0, pkh, pkl, 0,
             NTOK, D, D, D, D, D, 1, 1, 0,0,0,0,0,0, 0, 0, 2, 0, 0, 1);
        gemm(pyh, pyl, pwvh + wOff, pwvl + wOff, 0, pvth, pvtl, vb,
             NTOK, D, D, D, D, NTOK, 1, 1, 0,0,0,0,0,0, 1, 0, 0, 1, 0, 1);

        // scores[b,h] = q_bh [S,128] @ k_bh^T
        gemm(pqh, pql, pkh, pkl, sc, 0, 0, 0,
             S, S, DH, D, D, S,
             Bn * H, H, SD, 128, SD, 128, (ll)H * SS, SS,
             0, 0, 0, 0, 1, 0);

        softmax_k<<<Bn * H * S, 256>>>(x_len);

        // o[b,h] = probs [S,S] @ vT_bh^T
        gemm(pph, ppl, pvth, pvtl, 0, poh, pol, 0,
             S, DH, S, S, NTOK, D,
             Bn * H, H, (ll)H * SS, SS, S, (ll)128 * NTOK, SD, 128,
             0, 0, 0, 0, 0, 1);

        // out projection + residual
        gemm(poh, pol, pwoh + wOff, pwol + wOff, xs, 0, 0, ob,
             NTOK, D, D, D, D, D, 1, 1, 0,0,0,0,0,0, 1, 1, 0, 0, 1, 0);

        // MLP
        ln_k<<<NTOK, 256>>>(xs, mw, mb2);
        gemm(pyh, pyl, pw1h + mOff, pw1l + mOff, 0, pm1h, pm1l, b1,
             NTOK, Fdim, D, D, D, Fdim, 1, 1, 0,0,0,0,0,0, 1, 0, 1, 0, 0, 1);
        gemm(pm1h, pm1l, pw2h + mOff, pw2l + mOff, xs, 0, 0, b2,
             NTOK, D, Fdim, Fdim, Fdim, D, 1, 1, 0,0,0,0,0,0, 1, 1, 0, 0, 1, 0);
    }

    ll nh = (ll)NTOK * D;
    out_k<<<(int)((nh + 255) / 256), 256>>>((float*)d_out, x_len, (ll)out_size);
}

// round 7
// speedup vs baseline: 1.5065x; 1.3208x over previous
#include <cuda_runtime.h>
#include <cuda_fp16.h>
#include <math.h>

typedef long long ll;
typedef unsigned u32;

#define Bn 8
#define NMELS 128
#define TIN 4096
#define T1 2048
#define S 1024
#define D 1024
#define H 8
#define DH 128
#define Fdim 4096
#define NTOK (Bn*S)
#define Ldim 6

// ---------------- fp32 scratch ----------------
__device__ float g_h1[(size_t)Bn*T1*D];            // conv1 out [b][t][d]
__device__ float g_x [(size_t)NTOK*D];             // residual stream
__device__ float g_scores[(size_t)Bn*H*S*S];

// ---------------- fp16 buffers ----------------
// weights: hi/lo split; activations: single fp16
__device__ __align__(256) half c1h[(size_t)D*384],  c1l[(size_t)D*384];
__device__ __align__(256) half c2h[(size_t)D*3072], c2l[(size_t)D*3072];
__device__ __align__(256) half wqh[(size_t)Ldim*D*D], wql[(size_t)Ldim*D*D];
__device__ __align__(256) half wkh[(size_t)Ldim*D*D], wkl[(size_t)Ldim*D*D];
__device__ __align__(256) half wvh[(size_t)Ldim*D*D], wvl[(size_t)Ldim*D*D];
__device__ __align__(256) half woh[(size_t)Ldim*D*D], wol[(size_t)Ldim*D*D];
__device__ __align__(256) half w1h[(size_t)Ldim*Fdim*D], w1l[(size_t)Ldim*Fdim*D];
__device__ __align__(256) half w2h[(size_t)Ldim*Fdim*D], w2l[(size_t)Ldim*Fdim*D];
__device__ __align__(256) half g_col[(size_t)Bn*3072*S];
__device__ __align__(256) half g_y [(size_t)NTOK*D];
__device__ __align__(256) half g_q [(size_t)NTOK*D];
__device__ __align__(256) half g_kh[(size_t)NTOK*D], g_kl[(size_t)NTOK*D];
__device__ __align__(256) half g_vth[(size_t)D*NTOK], g_vtl[(size_t)D*NTOK];
__device__ __align__(256) half g_p [(size_t)Bn*H*S*S];
__device__ __align__(256) half g_m1[(size_t)NTOK*Fdim];
__device__ __align__(256) half g_o [(size_t)NTOK*D];

// ---------------- helpers ----------------
__device__ __forceinline__ float gelu_exact(float v) {
    return 0.5f * v * (1.0f + erff(v * 0.70710678118654752f));
}
__device__ __forceinline__ void splith(float v, half& h, half& l) {
    h = __float2half_rn(v);
    l = __float2half_rn(v - __half2float(h));
}
__device__ __forceinline__ void mma_fp16(float* d, const u32* a, const u32* b) {
    asm volatile(
        "mma.sync.aligned.m16n8k16.row.col.f32.f16.f16.f32 "
        "{%0,%1,%2,%3}, {%4,%5,%6,%7}, {%8,%9}, {%0,%1,%2,%3};\n"
        : "+f"(d[0]), "+f"(d[1]), "+f"(d[2]), "+f"(d[3])
        : "r"(a[0]), "r"(a[1]), "r"(a[2]), "r"(a[3]), "r"(b[0]), "r"(b[1]));
}
__device__ __forceinline__ void ldsm4(u32* r, u32 addr) {
    asm volatile("ldmatrix.sync.aligned.m8n8.x4.shared.b16 {%0,%1,%2,%3}, [%4];\n"
        : "=r"(r[0]), "=r"(r[1]), "=r"(r[2]), "=r"(r[3]) : "r"(addr));
}
__device__ __forceinline__ void cpa16(u32 dst, const void* src) {
    asm volatile("cp.async.cg.shared.global [%0], [%1], 16;\n" :: "r"(dst), "l"(src));
}

// ---------------- fp16x2 tensor-core GEMM (A single, B hi/lo; 16 warps, 3-stage) ----------------
// C[M,N] = A[M,K] * (Bh+Bl)[N,K]^T
#define KC 32
#define NSTG 3
#define PAD 40
#define TILE_E (128*PAD)             // fp16 elems per smem operand tile
#define STG_B  (3*TILE_E*2)          // bytes per stage (A,Bh,Bl) = 30720
#define SMEM_TOT (NSTG*STG_B)        // 92160

struct GemmP {
    const half *A, *Bh, *Bl;
    float* C; half *Cs; half *Ch, *Cl;
    const float* bias;
    int K, lda, ldb, ldc;
    int zDiv;
    ll sAo, sAi, sBo, sBi, sCo, sCi;
    int biasMode;   // 0 none, 1 per-col(n), 2 per-row(m)
    int addC;       // fp32 residual accumulate
    int act;        // 0 none, 1 exact GELU, 2 RoPE+scale (pairs of columns)
    int transStore; // store (m,n) at [n*ldc+m]
    int outF32, outHalf, outSplit;
};

__global__ __launch_bounds__(512, 1) void gemm_tc(GemmP p) {
    extern __shared__ __align__(16) half sm[];
    int z = blockIdx.z;
    ll offA = (ll)(z / p.zDiv) * p.sAo + (ll)(z % p.zDiv) * p.sAi;
    ll offB = (ll)(z / p.zDiv) * p.sBo + (ll)(z % p.zDiv) * p.sBi;
    ll offC = (ll)(z / p.zDiv) * p.sCo + (ll)(z % p.zDiv) * p.sCi;
    const half* A  = p.A  + offA;
    const half* Bh = p.Bh + offB;
    const half* Bl = p.Bl + offB;

    int m0 = blockIdx.y * 128, n0 = blockIdx.x * 128;
    int tid = threadIdx.x, lane = tid & 31, wid = tid >> 5;
    int wm = (wid & 3) * 32, wn = (wid >> 2) * 32;
    u32 smu = (u32)__cvta_generic_to_shared(sm);

    float acc[2][4][4];
    #pragma unroll
    for (int a = 0; a < 2; a++)
        #pragma unroll
        for (int b = 0; b < 4; b++)
            #pragma unroll
            for (int c = 0; c < 4; c++) acc[a][b][c] = 0.f;

    int ldRow = tid >> 2;       // 0..127
    int ldC   = tid & 3;        // 16B chunk within 32 k-elems

    auto issue = [&](int c) {
        u32 base = smu + (u32)(c % NSTG) * STG_B;
        int k0 = c * KC;
        u32 so = (u32)(ldRow * PAD + ldC * 8) * 2;
        ll ao = (ll)(m0 + ldRow) * p.lda + k0 + ldC * 8;
        ll bo = (ll)(n0 + ldRow) * p.ldb + k0 + ldC * 8;
        cpa16(base + 0 * TILE_E * 2 + so, A + ao);
        cpa16(base + 1 * TILE_E * 2 + so, Bh + bo);
        cpa16(base + 2 * TILE_E * 2 + so, Bl + bo);
        asm volatile("cp.async.commit_group;" ::: "memory");
    };

    int nch = p.K / KC;
    issue(0);
    if (nch > 1) issue(1);

    for (int c = 0; c < nch; c++) {
        if (c + 1 < nch) asm volatile("cp.async.wait_group 1;" ::: "memory");
        else             asm volatile("cp.async.wait_group 0;" ::: "memory");
        __syncthreads();
        if (c + 2 < nch) issue(c + 2);

        u32 aB  = smu + (u32)(c % NSTG) * STG_B;
        u32 bB  = aB + TILE_E * 2;
        u32 blB = aB + 2 * TILE_E * 2;

        #pragma unroll
        for (int ks = 0; ks < 2; ks++) {
            u32 ar[2][4], bh[4][2], bl[4][2];
            #pragma unroll
            for (int mi = 0; mi < 2; mi++) {
                int row = wm + mi * 16 + (lane & 15);
                int col = ks * 16 + (lane >> 4) * 8;
                u32 off = (u32)(row * PAD + col) * 2;
                ldsm4(ar[mi], aB + off);
            }
            #pragma unroll
            for (int nj = 0; nj < 2; nj++) {
                int g = lane >> 3;
                int row = wn + nj * 16 + ((g >> 1) << 3) + (lane & 7);
                int col = ks * 16 + ((g & 1) << 3);
                u32 off = (u32)(row * PAD + col) * 2;
                u32 t[4];
                ldsm4(t, bB + off);
                bh[nj*2][0] = t[0]; bh[nj*2][1] = t[1];
                bh[nj*2+1][0] = t[2]; bh[nj*2+1][1] = t[3];
                ldsm4(t, blB + off);
                bl[nj*2][0] = t[0]; bl[nj*2][1] = t[1];
                bl[nj*2+1][0] = t[2]; bl[nj*2+1][1] = t[3];
            }
            #pragma unroll
            for (int mi = 0; mi < 2; mi++)
                #pragma unroll
                for (int nf = 0; nf < 4; nf++)
                    mma_fp16(acc[mi][nf], ar[mi], bh[nf]);
            #pragma unroll
            for (int mi = 0; mi < 2; mi++)
                #pragma unroll
                for (int nf = 0; nf < 4; nf++)
                    mma_fp16(acc[mi][nf], ar[mi], bl[nf]);
        }
    }

    // ---- epilogue (register fragments; columns come in adjacent pairs) ----
    float* Cp  = p.C  ? p.C  + offC : nullptr;
    half* Csp  = p.Cs ? p.Cs + offC : nullptr;
    half* Chp  = p.Ch ? p.Ch + offC : nullptr;
    half* Clp  = p.Cl ? p.Cl + offC : nullptr;
    #pragma unroll
    for (int mi = 0; mi < 2; mi++)
        #pragma unroll
        for (int nf = 0; nf < 4; nf++) {
            int rB = m0 + wm + mi * 16 + (lane >> 2);
            int cB = n0 + wn + nf * 8 + (lane & 3) * 2;
            #pragma unroll
            for (int pe = 0; pe < 2; pe++) {
                int m = rB + pe * 8;
                float v0 = acc[mi][nf][pe * 2 + 0];
                float v1 = acc[mi][nf][pe * 2 + 1];
                if (p.biasMode == 1) { v0 += p.bias[cB]; v1 += p.bias[cB + 1]; }
                else if (p.biasMode == 2) { float bb = p.bias[m]; v0 += bb; v1 += bb; }
                if (p.act == 1) { v0 = gelu_exact(v0); v1 = gelu_exact(v1); }
                else if (p.act == 2) {
                    int s = m & (S - 1);
                    int j = (cB & 127) >> 1;
                    float freq = powf(10000.f, -(float)(2 * j) * (1.f / 128.f));
                    float ang = (float)s * freq;
                    float cc, ss; sincosf(ang, &ss, &cc);
                    const float sc = 0.29730177875068026f;  // 128^-0.25
                    float r0 = (v0 * cc - v1 * ss) * sc;
                    float r1 = (v0 * ss + v1 * cc) * sc;
                    v0 = r0; v1 = r1;
                }
                if (!p.transStore) {
                    ll off0 = (ll)m * p.ldc + cB;
                    if (p.outF32) {
                        float w0 = v0, w1 = v1;
                        if (p.addC) {
                            float2 o = *(float2*)&Cp[off0];
                            w0 += o.x; w1 += o.y;
                        }
                        *(float2*)&Cp[off0] = make_float2(w0, w1);
                    }
                    if (p.outHalf) {
                        half h0 = __float2half_rn(v0), h1 = __float2half_rn(v1);
                        u32 pk = (u32)__half_as_ushort(h0) | ((u32)__half_as_ushort(h1) << 16);
                        *(u32*)&Csp[off0] = pk;
                    }
                    if (p.outSplit) {
                        half h0, l0, h1, l1;
                        splith(v0, h0, l0); splith(v1, h1, l1);
                        u32 hp = (u32)__half_as_ushort(h0) | ((u32)__half_as_ushort(h1) << 16);
                        u32 lp = (u32)__half_as_ushort(l0) | ((u32)__half_as_ushort(l1) << 16);
                        *(u32*)&Chp[off0] = hp;
                        *(u32*)&Clp[off0] = lp;
                    }
                } else {
                    ll off0 = (ll)cB * p.ldc + m;
                    ll off1 = off0 + p.ldc;
                    if (p.outF32) {
                        float w0 = v0, w1 = v1;
                        if (p.addC) { w0 += Cp[off0]; w1 += Cp[off1]; }
                        Cp[off0] = w0; Cp[off1] = w1;
                    }
                    if (p.outHalf) {
                        Csp[off0] = __float2half_rn(v0);
                        Csp[off1] = __float2half_rn(v1);
                    }
                    if (p.outSplit) {
                        half h, l;
                        splith(v0, h, l); Chp[off0] = h; Clp[off0] = l;
                        splith(v1, h, l); Chp[off1] = h; Clp[off1] = l;
                    }
                }
            }
        }
}

// ---------------- weight split ----------------
__global__ void split_k(const float* __restrict__ in, half* __restrict__ hi,
                        half* __restrict__ lo, ll n) {
    ll i = ((ll)blockIdx.x * 256 + threadIdx.x) * 4;
    if (i >= n) return;
    float4 v = *(const float4*)&in[i];
    half h, l;
    splith(v.x, h, l); hi[i+0] = h; lo[i+0] = l;
    splith(v.y, h, l); hi[i+1] = h; lo[i+1] = l;
    splith(v.z, h, l); hi[i+2] = h; lo[i+2] = l;
    splith(v.w, h, l); hi[i+3] = h; lo[i+3] = l;
}

// ---------------- im2col ----------------
__global__ void im2col1_k(const float* __restrict__ x) {
    int idx = blockIdx.x * 256 + threadIdx.x;
    const int total = Bn * T1 * 384;
    if (idx >= total) return;
    int r = idx % 384;
    int t = (idx / 384) % T1;
    int b = idx / (384 * T1);
    int i = r / 3, kk = r % 3;
    int pos = 2 * t + kk - 1;
    float v = (pos >= 0 && pos < TIN) ? x[((ll)b * NMELS + i) * TIN + pos] : 0.f;
    g_col[idx] = __float2half_rn(v);
}
__global__ void im2col2_k() {
    ll idx = (ll)blockIdx.x * 256 + threadIdx.x;
    const ll total = (ll)Bn * S * 3072;
    if (idx >= total) return;
    int r = (int)(idx % 3072);
    int t = (int)((idx / 3072) % S);
    int b = (int)(idx / ((ll)S * 3072));
    int i = r / 3, kk = r % 3;
    int pos = 2 * t + kk - 1;
    float v = (pos >= 0 && pos < T1) ? g_h1[((ll)b * T1 + pos) * D + i] : 0.f;
    g_col[idx] = __float2half_rn(v);
}

// ---------------- LayerNorm -> fp16 ----------------
__global__ void ln_k(const float* __restrict__ x,
                     const float* __restrict__ w, const float* __restrict__ b) {
    int row = blockIdx.x;
    int tid = threadIdx.x;
    const float* xr = x + (ll)row * D;
    __shared__ float red[256];
    float v[4];
    #pragma unroll
    for (int i = 0; i < 4; i++) v[i] = xr[tid + 256 * i];
    float s = v[0] + v[1] + v[2] + v[3];
    red[tid] = s; __syncthreads();
    for (int o = 128; o > 0; o >>= 1) { if (tid < o) red[tid] += red[tid + o]; __syncthreads(); }
    float mean = red[0] * (1.f / D);
    __syncthreads();
    float sq = 0.f;
    #pragma unroll
    for (int i = 0; i < 4; i++) { float d0 = v[i] - mean; sq += d0 * d0; }
    red[tid] = sq; __syncthreads();
    for (int o = 128; o > 0; o >>= 1) { if (tid < o) red[tid] += red[tid + o]; __syncthreads(); }
    float rstd = rsqrtf(red[0] * (1.f / D) + 1e-5f);
    #pragma unroll
    for (int i = 0; i < 4; i++) {
        int c = tid + 256 * i;
        float y = (v[i] - mean) * rstd * w[c] + b[c];
        g_y[(ll)row * D + c] = __float2half_rn(y);
    }
}

// ---------------- masked softmax -> fp16 probs ----------------
__global__ void softmax_k(const int* __restrict__ x_len) {
    ll row = blockIdx.x;
    int b = (int)(row >> 13);
    const float* r = g_scores + row * S;
    int tid = threadIdx.x;
    int xl = x_len[b];
    __shared__ float red[256];
    float v[4];
    #pragma unroll
    for (int i = 0; i < 4; i++) {
        int j = tid + 256 * i;
        float bias = (4 * j + 3 < xl) ? 0.f : -1e10f;
        v[i] = r[j] + bias;
    }
    float m = fmaxf(fmaxf(v[0], v[1]), fmaxf(v[2], v[3]));
    red[tid] = m; __syncthreads();
    for (int o = 128; o > 0; o >>= 1) { if (tid < o) red[tid] = fmaxf(red[tid], red[tid + o]); __syncthreads(); }
    m = red[0]; __syncthreads();
    float s = 0.f;
    #pragma unroll
    for (int i = 0; i < 4; i++) { v[i] = expf(v[i] - m); s += v[i]; }
    red[tid] = s; __syncthreads();
    for (int o = 128; o > 0; o >>= 1) { if (tid < o) red[tid] += red[tid + o]; __syncthreads(); }
    float inv = 1.f / red[0];
    #pragma unroll
    for (int i = 0; i < 4; i++)
        g_p[row * S + tid + 256 * i] = __float2half_rn(v[i] * inv);
}

// ---------------- output ----------------
__global__ void out_k(float* __restrict__ out, const int* __restrict__ x_len, ll out_size) {
    ll i = (ll)blockIdx.x * 256 + threadIdx.x;
    const ll nh = (ll)NTOK * D;
    if (i < nh && i < out_size) out[i] = g_x[i];
    if (i < Bn) {
        ll pos = nh + i;
        if (pos < out_size) {
            int yl = (x_len[i] + 1) / 2;
            yl = (yl + 1) / 2;
            out[pos] = (float)yl;
        }
    }
}

// ---------------- host launcher ----------------
extern "C" void kernel_launch(void* const* d_in, const int* in_sizes, int n_in,
                              void* d_out, int out_size) {
    const float* x        = (const float*)d_in[0];
    const int*   x_len    = (const int*)  d_in[1];
    const float* conv1_w  = (const float*)d_in[2];
    const float* conv1_b  = (const float*)d_in[3];
    const float* conv2_w  = (const float*)d_in[4];
    const float* conv2_b  = (const float*)d_in[5];
    const float* attn_ln_w= (const float*)d_in[6];
    const float* attn_ln_b= (const float*)d_in[7];
    const float* q_w      = (const float*)d_in[8];
    const float* q_b      = (const float*)d_in[9];
    const float* k_w      = (const float*)d_in[10];
    const float* v_w      = (const float*)d_in[11];
    const float* v_b      = (const float*)d_in[12];
    const float* out_w    = (const float*)d_in[13];
    const float* out_b    = (const float*)d_in[14];
    const float* mlp_ln_w = (const float*)d_in[15];
    const float* mlp_ln_b = (const float*)d_in[16];
    const float* mlp1_w   = (const float*)d_in[17];
    const float* mlp1_b   = (const float*)d_in[18];
    const float* mlp2_w   = (const float*)d_in[19];
    const float* mlp2_b   = (const float*)d_in[20];

    cudaFuncSetAttribute(gemm_tc, cudaFuncAttributeMaxDynamicSharedMemorySize, SMEM_TOT);

    #define SYM(p, s) do { void* _t; cudaGetSymbolAddress(&_t, s); p = (decltype(p))_t; } while (0)
    float *h1, *xs, *sc;
    SYM(h1, g_h1); SYM(xs, g_x); SYM(sc, g_scores);
    half *pc1h,*pc1l,*pc2h,*pc2l,*pwqh,*pwql,*pwkh,*pwkl,*pwvh,*pwvl,*pwoh,*pwol;
    half *pw1h,*pw1l,*pw2h,*pw2l,*pcol,*py,*pq,*pkh,*pkl;
    half *pvth,*pvtl,*pp,*pm1,*po;
    SYM(pc1h, c1h); SYM(pc1l, c1l); SYM(pc2h, c2h); SYM(pc2l, c2l);
    SYM(pwqh, wqh); SYM(pwql, wql); SYM(pwkh, wkh); SYM(pwkl, wkl);
    SYM(pwvh, wvh); SYM(pwvl, wvl); SYM(pwoh, woh); SYM(pwol, wol);
    SYM(pw1h, w1h); SYM(pw1l, w1l); SYM(pw2h, w2h); SYM(pw2l, w2l);
    SYM(pcol, g_col); SYM(py, g_y); SYM(pq, g_q); SYM(pkh, g_kh); SYM(pkl, g_kl);
    SYM(pvth, g_vth); SYM(pvtl, g_vtl); SYM(pp, g_p);
    SYM(pm1, g_m1); SYM(po, g_o);

    auto split = [&](const float* in, half* hi, half* lo, ll n) {
        split_k<<<(int)((n / 4 + 255) / 256), 256>>>(in, hi, lo, n);
    };
    split(conv1_w, pc1h, pc1l, (ll)D * 384);
    split(conv2_w, pc2h, pc2l, (ll)D * 3072);
    split(q_w,   pwqh, pwql, (ll)Ldim * D * D);
    split(k_w,   pwkh, pwkl, (ll)Ldim * D * D);
    split(v_w,   pwvh, pwvl, (ll)Ldim * D * D);
    split(out_w, pwoh, pwol, (ll)Ldim * D * D);
    split(mlp1_w, pw1h, pw1l, (ll)Ldim * Fdim * D);
    split(mlp2_w, pw2h, pw2l, (ll)Ldim * Fdim * D);

    auto gemm = [&](const half* A, const half* Bh_, const half* Bl_,
                    float* C, half* Cs, half* Ch, half* Cl, const float* bias,
                    int M, int N, int K, int lda, int ldb, int ldc,
                    int nz, int zDiv,
                    ll sAo, ll sAi, ll sBo, ll sBi, ll sCo, ll sCi,
                    int biasMode, int addC, int act, int transStore,
                    int outF32, int outHalf, int outSplit) {
        GemmP p;
        p.A = A; p.Bh = Bh_; p.Bl = Bl_;
        p.C = C; p.Cs = Cs; p.Ch = Ch; p.Cl = Cl; p.bias = bias;
        p.K = K; p.lda = lda; p.ldb = ldb; p.ldc = ldc;
        p.zDiv = zDiv;
        p.sAo = sAo; p.sAi = sAi; p.sBo = sBo; p.sBi = sBi; p.sCo = sCo; p.sCi = sCi;
        p.biasMode = biasMode; p.addC = addC; p.act = act;
        p.transStore = transStore;
        p.outF32 = outF32; p.outHalf = outHalf; p.outSplit = outSplit;
        dim3 g(N / 128, M / 128, nz);
        gemm_tc<<<g, 512, SMEM_TOT>>>(p);
    };

    const ll SD = (ll)S * D;
    const ll SS = (ll)S * S;

    // conv1: A = im2col [b][t][384] (M=T1), B = W1 [D][384] hi/lo, C = g_h1 [b][t][d]
    im2col1_k<<<(Bn * T1 * 384 + 255) / 256, 256>>>(x);
    gemm(pcol, pc1h, pc1l, h1, 0, 0, 0, conv1_b,
         T1, 1024, 384, 384, 384, D,
         Bn, 1, (ll)T1 * 384, 0, 0, 0, (ll)T1 * D, 0,
         1, 0, 1, 0, 1, 0, 0);

    // conv2: A = im2col [b][t][3072] (M=S), B = W2 hi/lo, C = g_x [tok][d]
    im2col2_k<<<(int)(((ll)Bn * S * 3072 + 255) / 256), 256>>>();
    gemm(pcol, pc2h, pc2l, xs, 0, 0, 0, conv2_b,
         S, 1024, 3072, 3072, 3072, D,
         Bn, 1, (ll)S * 3072, 0, 0, 0, SD, 0,
         1, 0, 1, 0, 1, 0, 0);

    for (int l = 0; l < 6; l++) {
        const float* aw = attn_ln_w + l * D;  const float* ab = attn_ln_b + l * D;
        const float* qb = q_b + l * D;
        const float* vb = v_b + l * D;
        const float* ob = out_b + l * D;
        const float* mw = mlp_ln_w + l * D;   const float* mb2 = mlp_ln_b + l * D;
        const float* b1 = mlp1_b + l * Fdim;
        const float* b2 = mlp2_b + l * D;
        ll wOff = (ll)l * D * D;
        ll mOff = (ll)l * Fdim * D;

        ln_k<<<NTOK, 256>>>(xs, aw, ab);

        // q (RoPE, single fp16); k (RoPE, hi/lo split); v (transposed, hi/lo split)
        gemm(py, pwqh + wOff, pwql + wOff, 0, pq, 0, 0, qb,
             NTOK, D, D, D, D, D, 1, 1, 0,0,0,0,0,0, 1, 0, 2, 0, 0, 1, 0);
        gemm(py, pwkh + wOff, pwkl + wOff, 0, 0, pkh, pkl, 0,
             NTOK, D, D, D, D, D, 1, 1, 0,0,0,0,0,0, 0, 0, 2, 0, 0, 0, 1);
        gemm(py, pwvh + wOff, pwvl + wOff, 0, 0, pvth, pvtl, vb,
             NTOK, D, D, D, D, NTOK, 1, 1, 0,0,0,0,0,0, 1, 0, 0, 1, 0, 0, 1);

        // scores[b,h] = q_bh [S,128] @ (kh+kl)_bh^T
        gemm(pq, pkh, pkl, sc, 0, 0, 0, 0,
             S, S, DH, D, D, S,
             Bn * H, H, SD, 128, SD, 128, (ll)H * SS, SS,
             0, 0, 0, 0, 1, 0, 0);

        softmax_k<<<Bn * H * S, 256>>>(x_len);

        // o[b,h] = probs [S,S] @ (vTh+vTl)_bh^T -> single fp16
        gemm(pp, pvth, pvtl, 0, po, 0, 0, 0,
             S, DH, S, S, NTOK, D,
             Bn * H, H, (ll)H * SS, SS, S, (ll)128 * NTOK, SD, 128,
             0, 0, 0, 0, 0, 1, 0);

        // out projection + residual
        gemm(po, pwoh + wOff, pwol + wOff, xs, 0, 0, 0, ob,
             NTOK, D, D, D, D, D, 1, 1, 0,0,0,0,0,0, 1, 1, 0, 0, 1, 0, 0);

        // MLP
        ln_k<<<NTOK, 256>>>(xs, mw, mb2);
        gemm(py, pw1h + mOff, pw1l + mOff, 0, pm1, 0, 0, b1,
             NTOK, Fdim, D, D, D, Fdim, 1, 1, 0,0,0,0,0,0, 1, 0, 1, 0, 0, 1, 0);
        gemm(pm1, pw2h + mOff, pw2l + mOff, xs, 0, 0, 0, b2,
             NTOK, D, Fdim, Fdim, Fdim, D, 1, 1, 0,0,0,0,0,0, 1, 1, 0, 0, 1, 0, 0);
    }

    ll nh = (ll)NTOK * D;
    out_k<<<(int)((nh + 255) / 256), 256>>>((float*)d_out, x_len, (ll)out_size);
}

// round 8
// speedup vs baseline: 2.2452x; 1.4904x over previous
#include <cuda_runtime.h>
#include <cuda_fp16.h>
#include <math.h>

typedef long long ll;
typedef unsigned u32;

#define Bn 8
#define NMELS 128
#define TIN 4096
#define T1 2048
#define S 1024
#define D 1024
#define H 8
#define DH 128
#define Fdim 4096
#define NTOK (Bn*S)
#define Ldim 6

// ---------------- fp32 scratch ----------------
__device__ float g_x [(size_t)NTOK*D];             // residual stream
__device__ float g_scores[(size_t)Bn*H*S*S];

// ---------------- fp16 buffers ----------------
__device__ __align__(256) half g_h1[(size_t)Bn*T1*D];   // conv1 out [b][t][d]
__device__ __align__(256) half c1w[(size_t)D*384];
__device__ __align__(256) half c2w[(size_t)D*3072];
__device__ __align__(256) half wq[(size_t)Ldim*D*D];
__device__ __align__(256) half wk[(size_t)Ldim*D*D];
__device__ __align__(256) half wv[(size_t)Ldim*D*D];
__device__ __align__(256) half wo[(size_t)Ldim*D*D];
__device__ __align__(256) half w1[(size_t)Ldim*Fdim*D];
__device__ __align__(256) half w2[(size_t)Ldim*Fdim*D];
__device__ __align__(256) half g_col[(size_t)Bn*3072*S];
__device__ __align__(256) half g_y [(size_t)NTOK*D];
__device__ __align__(256) half g_q [(size_t)NTOK*D];
__device__ __align__(256) half g_k [(size_t)NTOK*D];
__device__ __align__(256) half g_vt[(size_t)D*NTOK];
__device__ __align__(256) half g_p [(size_t)Bn*H*S*S];
__device__ __align__(256) half g_m1[(size_t)NTOK*Fdim];
__device__ __align__(256) half g_o [(size_t)NTOK*D];

// ---------------- helpers ----------------
__device__ __forceinline__ float gelu_exact(float v) {
    return 0.5f * v * (1.0f + erff(v * 0.70710678118654752f));
}
__device__ __forceinline__ void mma_fp16(float* d, const u32* a, const u32* b) {
    asm volatile(
        "mma.sync.aligned.m16n8k16.row.col.f32.f16.f16.f32 "
        "{%0,%1,%2,%3}, {%4,%5,%6,%7}, {%8,%9}, {%0,%1,%2,%3};\n"
        : "+f"(d[0]), "+f"(d[1]), "+f"(d[2]), "+f"(d[3])
        : "r"(a[0]), "r"(a[1]), "r"(a[2]), "r"(a[3]), "r"(b[0]), "r"(b[1]));
}
__device__ __forceinline__ void ldsm4(u32* r, u32 addr) {
    asm volatile("ldmatrix.sync.aligned.m8n8.x4.shared.b16 {%0,%1,%2,%3}, [%4];\n"
        : "=r"(r[0]), "=r"(r[1]), "=r"(r[2]), "=r"(r[3]) : "r"(addr));
}
__device__ __forceinline__ void cpa16(u32 dst, const void* src) {
    asm volatile("cp.async.cg.shared.global [%0], [%1], 16;\n" :: "r"(dst), "l"(src));
}

// ---------------- fp16 tensor-core GEMM (16 warps, 3-stage cp.async) ----------------
// C[M,N] = A[M,K] * B[N,K]^T
#define KC 32
#define NSTG 3
#define PAD 40
#define TILE_E (128*PAD)             // fp16 elems per smem operand tile
#define STG_B  (2*TILE_E*2)          // bytes per stage (A,B) = 20480
#define SMEM_TOT (NSTG*STG_B)        // 61440

struct GemmP {
    const half *A, *B;
    float* C; half *Cs;
    const float* bias;
    int K, lda, ldb, ldc;
    int zDiv;
    ll sAo, sAi, sBo, sBi, sCo, sCi;
    int biasMode;   // 0 none, 1 per-col(n), 2 per-row(m)
    int addC;       // fp32 residual accumulate
    int act;        // 0 none, 1 exact GELU, 2 RoPE+scale (pairs of columns)
    int transStore; // store (m,n) at [n*ldc+m]
    int outF32, outHalf;
};

__global__ __launch_bounds__(512, 1) void gemm_tc(GemmP p) {
    extern __shared__ __align__(16) half sm[];
    int z = blockIdx.z;
    ll offA = (ll)(z / p.zDiv) * p.sAo + (ll)(z % p.zDiv) * p.sAi;
    ll offB = (ll)(z / p.zDiv) * p.sBo + (ll)(z % p.zDiv) * p.sBi;
    ll offC = (ll)(z / p.zDiv) * p.sCo + (ll)(z % p.zDiv) * p.sCi;
    const half* A = p.A + offA;
    const half* B = p.B + offB;

    int m0 = blockIdx.y * 128, n0 = blockIdx.x * 128;
    int tid = threadIdx.x, lane = tid & 31, wid = tid >> 5;
    int wm = (wid & 3) * 32, wn = (wid >> 2) * 32;
    u32 smu = (u32)__cvta_generic_to_shared(sm);

    float acc[2][4][4];
    #pragma unroll
    for (int a = 0; a < 2; a++)
        #pragma unroll
        for (int b = 0; b < 4; b++)
            #pragma unroll
            for (int c = 0; c < 4; c++) acc[a][b][c] = 0.f;

    int ldRow = tid >> 2;       // 0..127
    int ldC   = tid & 3;        // 16B chunk within 32 k-elems

    auto issue = [&](int c) {
        u32 base = smu + (u32)(c % NSTG) * STG_B;
        int k0 = c * KC;
        u32 so = (u32)(ldRow * PAD + ldC * 8) * 2;
        ll ao = (ll)(m0 + ldRow) * p.lda + k0 + ldC * 8;
        ll bo = (ll)(n0 + ldRow) * p.ldb + k0 + ldC * 8;
        cpa16(base + 0 * TILE_E * 2 + so, A + ao);
        cpa16(base + 1 * TILE_E * 2 + so, B + bo);
        asm volatile("cp.async.commit_group;" ::: "memory");
    };

    int nch = p.K / KC;
    issue(0);
    if (nch > 1) issue(1);

    for (int c = 0; c < nch; c++) {
        if (c + 1 < nch) asm volatile("cp.async.wait_group 1;" ::: "memory");
        else             asm volatile("cp.async.wait_group 0;" ::: "memory");
        __syncthreads();
        if (c + 2 < nch) issue(c + 2);

        u32 aB = smu + (u32)(c % NSTG) * STG_B;
        u32 bB = aB + TILE_E * 2;

        #pragma unroll
        for (int ks = 0; ks < 2; ks++) {
            u32 ar[2][4], br[4][2];
            #pragma unroll
            for (int mi = 0; mi < 2; mi++) {
                int row = wm + mi * 16 + (lane & 15);
                int col = ks * 16 + (lane >> 4) * 8;
                u32 off = (u32)(row * PAD + col) * 2;
                ldsm4(ar[mi], aB + off);
            }
            #pragma unroll
            for (int nj = 0; nj < 2; nj++) {
                int g = lane >> 3;
                int row = wn + nj * 16 + ((g >> 1) << 3) + (lane & 7);
                int col = ks * 16 + ((g & 1) << 3);
                u32 off = (u32)(row * PAD + col) * 2;
                u32 t[4];
                ldsm4(t, bB + off);
                br[nj*2][0] = t[0]; br[nj*2][1] = t[1];
                br[nj*2+1][0] = t[2]; br[nj*2+1][1] = t[3];
            }
            #pragma unroll
            for (int mi = 0; mi < 2; mi++)
                #pragma unroll
                for (int nf = 0; nf < 4; nf++)
                    mma_fp16(acc[mi][nf], ar[mi], br[nf]);
        }
    }

    // ---- epilogue (register fragments; columns come in adjacent pairs) ----
    float* Cp = p.C  ? p.C  + offC : nullptr;
    half* Csp = p.Cs ? p.Cs + offC : nullptr;
    #pragma unroll
    for (int mi = 0; mi < 2; mi++)
        #pragma unroll
        for (int nf = 0; nf < 4; nf++) {
            int rB = m0 + wm + mi * 16 + (lane >> 2);
            int cB = n0 + wn + nf * 8 + (lane & 3) * 2;
            #pragma unroll
            for (int pe = 0; pe < 2; pe++) {
                int m = rB + pe * 8;
                float v0 = acc[mi][nf][pe * 2 + 0];
                float v1 = acc[mi][nf][pe * 2 + 1];
                if (p.biasMode == 1) { v0 += p.bias[cB]; v1 += p.bias[cB + 1]; }
                else if (p.biasMode == 2) { float bb = p.bias[m]; v0 += bb; v1 += bb; }
                if (p.act == 1) { v0 = gelu_exact(v0); v1 = gelu_exact(v1); }
                else if (p.act == 2) {
                    int s = m & (S - 1);
                    int j = (cB & 127) >> 1;
                    float freq = powf(10000.f, -(float)(2 * j) * (1.f / 128.f));
                    float ang = (float)s * freq;
                    float cc, ss; sincosf(ang, &ss, &cc);
                    const float sc = 0.29730177875068026f;  // 128^-0.25
                    float r0 = (v0 * cc - v1 * ss) * sc;
                    float r1 = (v0 * ss + v1 * cc) * sc;
                    v0 = r0; v1 = r1;
                }
                if (!p.transStore) {
                    ll off0 = (ll)m * p.ldc + cB;
                    if (p.outF32) {
                        float w0 = v0, w1 = v1;
                        if (p.addC) {
                            float2 o = *(float2*)&Cp[off0];
                            w0 += o.x; w1 += o.y;
                        }
                        *(float2*)&Cp[off0] = make_float2(w0, w1);
                    }
                    if (p.outHalf) {
                        half h0 = __float2half_rn(v0), h1 = __float2half_rn(v1);
                        u32 pk = (u32)__half_as_ushort(h0) | ((u32)__half_as_ushort(h1) << 16);
                        *(u32*)&Csp[off0] = pk;
                    }
                } else {
                    ll off0 = (ll)cB * p.ldc + m;
                    ll off1 = off0 + p.ldc;
                    if (p.outF32) {
                        float w0 = v0, w1 = v1;
                        if (p.addC) { w0 += Cp[off0]; w1 += Cp[off1]; }
                        Cp[off0] = w0; Cp[off1] = w1;
                    }
                    if (p.outHalf) {
                        Csp[off0] = __float2half_rn(v0);
                        Csp[off1] = __float2half_rn(v1);
                    }
                }
            }
        }
}

// ---------------- weight convert fp32 -> fp16 ----------------
__global__ void cvt_k(const float* __restrict__ in, half* __restrict__ out, ll n) {
    ll i = ((ll)blockIdx.x * 256 + threadIdx.x) * 4;
    if (i >= n) return;
    float4 v = *(const float4*)&in[i];
    out[i+0] = __float2half_rn(v.x);
    out[i+1] = __float2half_rn(v.y);
    out[i+2] = __float2half_rn(v.z);
    out[i+3] = __float2half_rn(v.w);
}

// ---------------- im2col ----------------
__global__ void im2col1_k(const float* __restrict__ x) {
    int idx = blockIdx.x * 256 + threadIdx.x;
    const int total = Bn * T1 * 384;
    if (idx >= total) return;
    int r = idx % 384;
    int t = (idx / 384) % T1;
    int b = idx / (384 * T1);
    int i = r / 3, kk = r % 3;
    int pos = 2 * t + kk - 1;
    float v = (pos >= 0 && pos < TIN) ? x[((ll)b * NMELS + i) * TIN + pos] : 0.f;
    g_col[idx] = __float2half_rn(v);
}
__global__ void im2col2_k() {
    ll idx = (ll)blockIdx.x * 256 + threadIdx.x;
    const ll total = (ll)Bn * S * 3072;
    if (idx >= total) return;
    int r = (int)(idx % 3072);
    int t = (int)((idx / 3072) % S);
    int b = (int)(idx / ((ll)S * 3072));
    int i = r / 3, kk = r % 3;
    int pos = 2 * t + kk - 1;
    g_col[idx] = (pos >= 0 && pos < T1) ? g_h1[((ll)b * T1 + pos) * D + i] : __float2half_rn(0.f);
}

// ---------------- LayerNorm -> fp16 ----------------
__global__ void ln_k(const float* __restrict__ x,
                     const float* __restrict__ w, const float* __restrict__ b) {
    int row = blockIdx.x;
    int tid = threadIdx.x;
    const float* xr = x + (ll)row * D;
    __shared__ float red[256];
    float v[4];
    #pragma unroll
    for (int i = 0; i < 4; i++) v[i] = xr[tid + 256 * i];
    float s = v[0] + v[1] + v[2] + v[3];
    red[tid] = s; __syncthreads();
    for (int o = 128; o > 0; o >>= 1) { if (tid < o) red[tid] += red[tid + o]; __syncthreads(); }
    float mean = red[0] * (1.f / D);
    __syncthreads();
    float sq = 0.f;
    #pragma unroll
    for (int i = 0; i < 4; i++) { float d0 = v[i] - mean; sq += d0 * d0; }
    red[tid] = sq; __syncthreads();
    for (int o = 128; o > 0; o >>= 1) { if (tid < o) red[tid] += red[tid + o]; __syncthreads(); }
    float rstd = rsqrtf(red[0] * (1.f / D) + 1e-5f);
    #pragma unroll
    for (int i = 0; i < 4; i++) {
        int c = tid + 256 * i;
        float y = (v[i] - mean) * rstd * w[c] + b[c];
        g_y[(ll)row * D + c] = __float2half_rn(y);
    }
}

// ---------------- masked softmax -> fp16 probs ----------------
__global__ void softmax_k(const int* __restrict__ x_len) {
    ll row = blockIdx.x;
    int b = (int)(row >> 13);
    const float* r = g_scores + row * S;
    int tid = threadIdx.x;
    int xl = x_len[b];
    __shared__ float red[256];
    float v[4];
    #pragma unroll
    for (int i = 0; i < 4; i++) {
        int j = tid + 256 * i;
        float bias = (4 * j + 3 < xl) ? 0.f : -1e10f;
        v[i] = r[j] + bias;
    }
    float m = fmaxf(fmaxf(v[0], v[1]), fmaxf(v[2], v[3]));
    red[tid] = m; __syncthreads();
    for (int o = 128; o > 0; o >>= 1) { if (tid < o) red[tid] = fmaxf(red[tid], red[tid + o]); __syncthreads(); }
    m = red[0]; __syncthreads();
    float s = 0.f;
    #pragma unroll
    for (int i = 0; i < 4; i++) { v[i] = expf(v[i] - m); s += v[i]; }
    red[tid] = s; __syncthreads();
    for (int o = 128; o > 0; o >>= 1) { if (tid < o) red[tid] += red[tid + o]; __syncthreads(); }
    float inv = 1.f / red[0];
    #pragma unroll
    for (int i = 0; i < 4; i++)
        g_p[row * S + tid + 256 * i] = __float2half_rn(v[i] * inv);
}

// ---------------- output ----------------
__global__ void out_k(float* __restrict__ out, const int* __restrict__ x_len, ll out_size) {
    ll i = (ll)blockIdx.x * 256 + threadIdx.x;
    const ll nh = (ll)NTOK * D;
    if (i < nh && i < out_size) out[i] = g_x[i];
    if (i < Bn) {
        ll pos = nh + i;
        if (pos < out_size) {
            int yl = (x_len[i] + 1) / 2;
            yl = (yl + 1) / 2;
            out[pos] = (float)yl;
        }
    }
}

// ---------------- host launcher ----------------
extern "C" void kernel_launch(void* const* d_in, const int* in_sizes, int n_in,
                              void* d_out, int out_size) {
    const float* x        = (const float*)d_in[0];
    const int*   x_len    = (const int*)  d_in[1];
    const float* conv1_w  = (const float*)d_in[2];
    const float* conv1_b  = (const float*)d_in[3];
    const float* conv2_w  = (const float*)d_in[4];
    const float* conv2_b  = (const float*)d_in[5];
    const float* attn_ln_w= (const float*)d_in[6];
    const float* attn_ln_b= (const float*)d_in[7];
    const float* q_w      = (const float*)d_in[8];
    const float* q_b      = (const float*)d_in[9];
    const float* k_w      = (const float*)d_in[10];
    const float* v_w      = (const float*)d_in[11];
    const float* v_b      = (const float*)d_in[12];
    const float* out_w    = (const float*)d_in[13];
    const float* out_b    = (const float*)d_in[14];
    const float* mlp_ln_w = (const float*)d_in[15];
    const float* mlp_ln_b = (const float*)d_in[16];
    const float* mlp1_w   = (const float*)d_in[17];
    const float* mlp1_b   = (const float*)d_in[18];
    const float* mlp2_w   = (const float*)d_in[19];
    const float* mlp2_b   = (const float*)d_in[20];

    cudaFuncSetAttribute(gemm_tc, cudaFuncAttributeMaxDynamicSharedMemorySize, SMEM_TOT);

    #define SYM(p, s) do { void* _t; cudaGetSymbolAddress(&_t, s); p = (decltype(p))_t; } while (0)
    float *xs, *sc;
    SYM(xs, g_x); SYM(sc, g_scores);
    half *ph1, *pc1, *pc2, *pwq, *pwk, *pwv, *pwo, *pw1, *pw2;
    half *pcol, *py, *pq, *pk, *pvt, *pp, *pm1, *po;
    SYM(ph1, g_h1);
    SYM(pc1, c1w); SYM(pc2, c2w);
    SYM(pwq, wq); SYM(pwk, wk); SYM(pwv, wv); SYM(pwo, wo);
    SYM(pw1, w1); SYM(pw2, w2);
    SYM(pcol, g_col); SYM(py, g_y); SYM(pq, g_q); SYM(pk, g_k);
    SYM(pvt, g_vt); SYM(pp, g_p); SYM(pm1, g_m1); SYM(po, g_o);

    auto cvt = [&](const float* in, half* out, ll n) {
        cvt_k<<<(int)((n / 4 + 255) / 256), 256>>>(in, out, n);
    };
    cvt(conv1_w, pc1, (ll)D * 384);
    cvt(conv2_w, pc2, (ll)D * 3072);
    cvt(q_w,   pwq, (ll)Ldim * D * D);
    cvt(k_w,   pwk, (ll)Ldim * D * D);
    cvt(v_w,   pwv, (ll)Ldim * D * D);
    cvt(out_w, pwo, (ll)Ldim * D * D);
    cvt(mlp1_w, pw1, (ll)Ldim * Fdim * D);
    cvt(mlp2_w, pw2, (ll)Ldim * Fdim * D);

    auto gemm = [&](const half* A, const half* B,
                    float* C, half* Cs, const float* bias,
                    int M, int N, int K, int lda, int ldb, int ldc,
                    int nz, int zDiv,
                    ll sAo, ll sAi, ll sBo, ll sBi, ll sCo, ll sCi,
                    int biasMode, int addC, int act, int transStore,
                    int outF32, int outHalf) {
        GemmP p;
        p.A = A; p.B = B;
        p.C = C; p.Cs = Cs; p.bias = bias;
        p.K = K; p.lda = lda; p.ldb = ldb; p.ldc = ldc;
        p.zDiv = zDiv;
        p.sAo = sAo; p.sAi = sAi; p.sBo = sBo; p.sBi = sBi; p.sCo = sCo; p.sCi = sCi;
        p.biasMode = biasMode; p.addC = addC; p.act = act;
        p.transStore = transStore;
        p.outF32 = outF32; p.outHalf = outHalf;
        dim3 g(N / 128, M / 128, nz);
        gemm_tc<<<g, 512, SMEM_TOT>>>(p);
    };

    const ll SD = (ll)S * D;
    const ll SS = (ll)S * S;

    // conv1: A = im2col [b][t][384] (M=T1), B = W1 [D][384], C = g_h1 [b][t][d] fp16
    im2col1_k<<<(Bn * T1 * 384 + 255) / 256, 256>>>(x);
    gemm(pcol, pc1, 0, ph1, conv1_b,
         T1, 1024, 384, 384, 384, D,
         Bn, 1, (ll)T1 * 384, 0, 0, 0, (ll)T1 * D, 0,
         1, 0, 1, 0, 0, 1);

    // conv2: A = im2col [b][t][3072] (M=S), B = W2, C = g_x [tok][d] fp32
    im2col2_k<<<(int)(((ll)Bn * S * 3072 + 255) / 256), 256>>>();
    gemm(pcol, pc2, xs, 0, conv2_b,
         S, 1024, 3072, 3072, 3072, D,
         Bn, 1, (ll)S * 3072, 0, 0, 0, SD, 0,
         1, 0, 1, 0, 1, 0);

    for (int l = 0; l < 6; l++) {
        const float* aw = attn_ln_w + l * D;  const float* ab = attn_ln_b + l * D;
        const float* qb = q_b + l * D;
        const float* vb = v_b + l * D;
        const float* ob = out_b + l * D;
        const float* mw = mlp_ln_w + l * D;   const float* mb2 = mlp_ln_b + l * D;
        const float* b1 = mlp1_b + l * Fdim;
        const float* b2 = mlp2_b + l * D;
        ll wOff = (ll)l * D * D;
        ll mOff = (ll)l * Fdim * D;

        ln_k<<<NTOK, 256>>>(xs, aw, ab);

        // q, k (RoPE+scale epilogue, fp16); v (transposed [d][tok], fp16)
        gemm(py, pwq + wOff, 0, pq, qb,
             NTOK, D, D, D, D, D, 1, 1, 0,0,0,0,0,0, 1, 0, 2, 0, 0, 1);
        gemm(py, pwk + wOff, 0, pk, 0,
             NTOK, D, D, D, D, D, 1, 1, 0,0,0,0,0,0, 0, 0, 2, 0, 0, 1);
        gemm(py, pwv + wOff, 0, pvt, vb,
             NTOK, D, D, D, D, NTOK, 1, 1, 0,0,0,0,0,0, 1, 0, 0, 1, 0, 1);

        // scores[b,h] = q_bh [S,128] @ k_bh^T -> fp32
        gemm(pq, pk, sc, 0, 0,
             S, S, DH, D, D, S,
             Bn * H, H, SD, 128, SD, 128, (ll)H * SS, SS,
             0, 0, 0, 0, 1, 0);

        softmax_k<<<Bn * H * S, 256>>>(x_len);

        // o[b,h] = probs [S,S] @ vT_bh^T -> fp16
        gemm(pp, pvt, 0, po, 0,
             S, DH, S, S, NTOK, D,
             Bn * H, H, (ll)H * SS, SS, S, (ll)128 * NTOK, SD, 128,
             0, 0, 0, 0, 0, 1);

        // out projection + residual
        gemm(po, pwo + wOff, xs, 0, ob,
             NTOK, D, D, D, D, D, 1, 1, 0,0,0,0,0,0, 1, 1, 0, 0, 1, 0);

        // MLP
        ln_k<<<NTOK, 256>>>(xs, mw, mb2);
        gemm(py, pw1 + mOff, 0, pm1, b1,
             NTOK, Fdim, D, D, D, Fdim, 1, 1, 0,0,0,0,0,0, 1, 0, 1, 0, 0, 1);
        gemm(pm1, pw2 + mOff, xs, 0, b2,
             NTOK, D, Fdim, Fdim, Fdim, D, 1, 1, 0,0,0,0,0,0, 1, 1, 0, 0, 1, 0);
    }

    ll nh = (ll)NTOK * D;
    out_k<<<(int)((nh + 255) / 256), 256>>>((float*)d_out, x_len, (ll)out_size);
}

// round 9
// speedup vs baseline: 2.6648x; 1.1869x over previous
#include <cuda_runtime.h>
#include <cuda_fp16.h>
#include <math.h>

typedef long long ll;
typedef unsigned u32;

#define Bn 8
#define NMELS 128
#define TIN 4096
#define T1 2048
#define S 1024
#define D 1024
#define H 8
#define DH 128
#define Fdim 4096
#define NTOK (Bn*S)
#define Ldim 6

// ---------------- fp32 scratch ----------------
__device__ float g_x [(size_t)NTOK*D];             // residual stream

// ---------------- fp16 buffers ----------------
__device__ __align__(256) half g_h1[(size_t)Bn*T1*D];   // conv1 out [b][t][d]
__device__ __align__(256) half c1w[(size_t)D*384];
__device__ __align__(256) half c2w[(size_t)D*3072];
__device__ __align__(256) half wq[(size_t)Ldim*D*D];
__device__ __align__(256) half wk[(size_t)Ldim*D*D];
__device__ __align__(256) half wv[(size_t)Ldim*D*D];
__device__ __align__(256) half wo[(size_t)Ldim*D*D];
__device__ __align__(256) half w1[(size_t)Ldim*Fdim*D];
__device__ __align__(256) half w2[(size_t)Ldim*Fdim*D];
__device__ __align__(256) half g_col[(size_t)Bn*3072*S];
__device__ __align__(256) half g_y [(size_t)NTOK*D];
__device__ __align__(256) half g_q [(size_t)NTOK*D];
__device__ __align__(256) half g_k [(size_t)NTOK*D];
__device__ __align__(256) half g_vt[(size_t)D*NTOK];
__device__ __align__(256) half g_m1[(size_t)NTOK*Fdim];
__device__ __align__(256) half g_o [(size_t)NTOK*D];

// ---------------- helpers ----------------
__device__ __forceinline__ float gelu_exact(float v) {
    return 0.5f * v * (1.0f + erff(v * 0.70710678118654752f));
}
__device__ __forceinline__ void mma_fp16(float* d, const u32* a, const u32* b) {
    asm volatile(
        "mma.sync.aligned.m16n8k16.row.col.f32.f16.f16.f32 "
        "{%0,%1,%2,%3}, {%4,%5,%6,%7}, {%8,%9}, {%0,%1,%2,%3};\n"
        : "+f"(d[0]), "+f"(d[1]), "+f"(d[2]), "+f"(d[3])
        : "r"(a[0]), "r"(a[1]), "r"(a[2]), "r"(a[3]), "r"(b[0]), "r"(b[1]));
}
__device__ __forceinline__ void ldsm4(u32* r, u32 addr) {
    asm volatile("ldmatrix.sync.aligned.m8n8.x4.shared.b16 {%0,%1,%2,%3}, [%4];\n"
        : "=r"(r[0]), "=r"(r[1]), "=r"(r[2]), "=r"(r[3]) : "r"(addr));
}
__device__ __forceinline__ void cpa16(u32 dst, const void* src) {
    asm volatile("cp.async.cg.shared.global [%0], [%1], 16;\n" :: "r"(dst), "l"(src));
}
__device__ __forceinline__ u32 packh2(float lo, float hi) {
    __half2 h = __floats2half2_rn(lo, hi);
    return *(u32*)&h;
}

// ---------------- fp16 tensor-core GEMM (16 warps, 3-stage cp.async) ----------------
// C[M,N] = A[M,K] * B[N,K]^T
#define KC 32
#define NSTG 3
#define PAD 40
#define TILE_E (128*PAD)
#define STG_B  (2*TILE_E*2)
#define SMEM_TOT (NSTG*STG_B)        // 61440

struct GemmP {
    const half *A, *B;
    float* C; half *Cs;
    const float* bias;
    int K, lda, ldb, ldc;
    int zDiv;
    ll sAo, sAi, sBo, sBi, sCo, sCi;
    int biasMode;   // 0 none, 1 per-col(n), 2 per-row(m)
    int addC;
    int act;        // 0 none, 1 exact GELU, 2 RoPE+scale
    int transStore;
    int outF32, outHalf;
};

__global__ __launch_bounds__(512, 1) void gemm_tc(GemmP p) {
    extern __shared__ __align__(16) half sm[];
    int z = blockIdx.z;
    ll offA = (ll)(z / p.zDiv) * p.sAo + (ll)(z % p.zDiv) * p.sAi;
    ll offB = (ll)(z / p.zDiv) * p.sBo + (ll)(z % p.zDiv) * p.sBi;
    ll offC = (ll)(z / p.zDiv) * p.sCo + (ll)(z % p.zDiv) * p.sCi;
    const half* A = p.A + offA;
    const half* B = p.B + offB;

    int m0 = blockIdx.y * 128, n0 = blockIdx.x * 128;
    int tid = threadIdx.x, lane = tid & 31, wid = tid >> 5;
    int wm = (wid & 3) * 32, wn = (wid >> 2) * 32;
    u32 smu = (u32)__cvta_generic_to_shared(sm);

    float acc[2][4][4];
    #pragma unroll
    for (int a = 0; a < 2; a++)
        #pragma unroll
        for (int b = 0; b < 4; b++)
            #pragma unroll
            for (int c = 0; c < 4; c++) acc[a][b][c] = 0.f;

    int ldRow = tid >> 2;
    int ldC   = tid & 3;

    auto issue = [&](int c) {
        u32 base = smu + (u32)(c % NSTG) * STG_B;
        int k0 = c * KC;
        u32 so = (u32)(ldRow * PAD + ldC * 8) * 2;
        ll ao = (ll)(m0 + ldRow) * p.lda + k0 + ldC * 8;
        ll bo = (ll)(n0 + ldRow) * p.ldb + k0 + ldC * 8;
        cpa16(base + 0 * TILE_E * 2 + so, A + ao);
        cpa16(base + 1 * TILE_E * 2 + so, B + bo);
        asm volatile("cp.async.commit_group;" ::: "memory");
    };

    int nch = p.K / KC;
    issue(0);
    if (nch > 1) issue(1);

    for (int c = 0; c < nch; c++) {
        if (c + 1 < nch) asm volatile("cp.async.wait_group 1;" ::: "memory");
        else             asm volatile("cp.async.wait_group 0;" ::: "memory");
        __syncthreads();
        if (c + 2 < nch) issue(c + 2);

        u32 aB = smu + (u32)(c % NSTG) * STG_B;
        u32 bB = aB + TILE_E * 2;

        #pragma unroll
        for (int ks = 0; ks < 2; ks++) {
            u32 ar[2][4], br[4][2];
            #pragma unroll
            for (int mi = 0; mi < 2; mi++) {
                int row = wm + mi * 16 + (lane & 15);
                int col = ks * 16 + (lane >> 4) * 8;
                ldsm4(ar[mi], aB + (u32)(row * PAD + col) * 2);
            }
            #pragma unroll
            for (int nj = 0; nj < 2; nj++) {
                int g = lane >> 3;
                int row = wn + nj * 16 + ((g >> 1) << 3) + (lane & 7);
                int col = ks * 16 + ((g & 1) << 3);
                u32 t[4];
                ldsm4(t, bB + (u32)(row * PAD + col) * 2);
                br[nj*2][0] = t[0]; br[nj*2][1] = t[1];
                br[nj*2+1][0] = t[2]; br[nj*2+1][1] = t[3];
            }
            #pragma unroll
            for (int mi = 0; mi < 2; mi++)
                #pragma unroll
                for (int nf = 0; nf < 4; nf++)
                    mma_fp16(acc[mi][nf], ar[mi], br[nf]);
        }
    }

    float* Cp = p.C  ? p.C  + offC : nullptr;
    half* Csp = p.Cs ? p.Cs + offC : nullptr;
    #pragma unroll
    for (int mi = 0; mi < 2; mi++)
        #pragma unroll
        for (int nf = 0; nf < 4; nf++) {
            int rB = m0 + wm + mi * 16 + (lane >> 2);
            int cB = n0 + wn + nf * 8 + (lane & 3) * 2;
            #pragma unroll
            for (int pe = 0; pe < 2; pe++) {
                int m = rB + pe * 8;
                float v0 = acc[mi][nf][pe * 2 + 0];
                float v1 = acc[mi][nf][pe * 2 + 1];
                if (p.biasMode == 1) { v0 += p.bias[cB]; v1 += p.bias[cB + 1]; }
                else if (p.biasMode == 2) { float bb = p.bias[m]; v0 += bb; v1 += bb; }
                if (p.act == 1) { v0 = gelu_exact(v0); v1 = gelu_exact(v1); }
                else if (p.act == 2) {
                    int s = m & (S - 1);
                    int j = (cB & 127) >> 1;
                    float freq = powf(10000.f, -(float)(2 * j) * (1.f / 128.f));
                    float ang = (float)s * freq;
                    float cc, ss; sincosf(ang, &ss, &cc);
                    const float sc = 0.29730177875068026f;  // 128^-0.25
                    float r0 = (v0 * cc - v1 * ss) * sc;
                    float r1 = (v0 * ss + v1 * cc) * sc;
                    v0 = r0; v1 = r1;
                }
                if (!p.transStore) {
                    ll off0 = (ll)m * p.ldc + cB;
                    if (p.outF32) {
                        float w0 = v0, w1 = v1;
                        if (p.addC) {
                            float2 o = *(float2*)&Cp[off0];
                            w0 += o.x; w1 += o.y;
                        }
                        *(float2*)&Cp[off0] = make_float2(w0, w1);
                    }
                    if (p.outHalf) *(u32*)&Csp[off0] = packh2(v0, v1);
                } else {
                    ll off0 = (ll)cB * p.ldc + m;
                    ll off1 = off0 + p.ldc;
                    if (p.outF32) {
                        float w0 = v0, w1 = v1;
                        if (p.addC) { w0 += Cp[off0]; w1 += Cp[off1]; }
                        Cp[off0] = w0; Cp[off1] = w1;
                    }
                    if (p.outHalf) {
                        Csp[off0] = __float2half_rn(v0);
                        Csp[off1] = __float2half_rn(v1);
                    }
                }
            }
        }
}

// ---------------- fused flash attention ----------------
// grid (S/64, Bn*H); 128 threads; Q block 64 rows; kv tiles of 128.
#define FP2 136
#define FSM_BYTES ((64+128+128)*FP2*2)    // 87040

__global__ __launch_bounds__(128) void attn_k(const int* __restrict__ x_len) {
    extern __shared__ __align__(16) half fsm[];
    int tid = threadIdx.x, lane = tid & 31, wid = tid >> 5;
    int bh = blockIdx.y, b = bh >> 3, h = bh & 7;
    int m0 = blockIdx.x * 64;
    int wm = wid * 16;
    u32 smu = (u32)__cvta_generic_to_shared(fsm);
    u32 sQ = smu;
    u32 sK = smu + (u32)(64 * FP2) * 2;
    u32 sV = sK + (u32)(128 * FP2) * 2;

    const half* qp = g_q + ((ll)(b * S + m0)) * D + h * 128;
    const half* kp = g_k + ((ll)b * S) * D + h * 128;
    const half* vp = g_vt + ((ll)(h * 128)) * NTOK + (ll)b * S;

    // load Q (64 x 128)
    #pragma unroll
    for (int i = 0; i < 8; i++) {
        int idx = tid + 128 * i, row = idx >> 4, ch = idx & 15;
        cpa16(sQ + (u32)(row * FP2 + ch * 8) * 2, qp + (ll)row * D + ch * 8);
    }
    asm volatile("cp.async.commit_group;" ::: "memory");

    int xl = x_len[b];
    int quad = lane >> 2, qi = lane & 3;
    float mrow[2] = {-1e30f, -1e30f}, lrow[2] = {0.f, 0.f};
    float oacc[16][4];
    #pragma unroll
    for (int nt = 0; nt < 16; nt++)
        #pragma unroll
        for (int e = 0; e < 4; e++) oacc[nt][e] = 0.f;

    for (int kv0 = 0; kv0 < S; kv0 += 128) {
        if (kv0) __syncthreads();   // all reads of previous K/V done
        #pragma unroll
        for (int i = 0; i < 16; i++) {
            int idx = tid + 128 * i, row = idx >> 4, ch = idx & 15;
            cpa16(sK + (u32)(row * FP2 + ch * 8) * 2, kp + (ll)(kv0 + row) * D + ch * 8);
            cpa16(sV + (u32)(row * FP2 + ch * 8) * 2, vp + (ll)row * NTOK + kv0 + ch * 8);
        }
        asm volatile("cp.async.commit_group;" ::: "memory");
        asm volatile("cp.async.wait_group 0;" ::: "memory");
        __syncthreads();

        // S = Q @ K^T  (m16 x n128 x k128 per warp)
        float sacc[16][4];
        #pragma unroll
        for (int nt = 0; nt < 16; nt++)
            #pragma unroll
            for (int e = 0; e < 4; e++) sacc[nt][e] = 0.f;

        #pragma unroll
        for (int ks = 0; ks < 8; ks++) {
            u32 aq[4];
            ldsm4(aq, sQ + (u32)((wm + (lane & 15)) * FP2 + ks * 16 + (lane >> 4) * 8) * 2);
            #pragma unroll
            for (int njp = 0; njp < 8; njp++) {
                int g = lane >> 3;
                int row = njp * 16 + ((g >> 1) << 3) + (lane & 7);
                int col = ks * 16 + ((g & 1) << 3);
                u32 t[4];
                ldsm4(t, sK + (u32)(row * FP2 + col) * 2);
                u32 b0[2] = {t[0], t[1]}, b1[2] = {t[2], t[3]};
                mma_fp16(sacc[njp*2],   aq, b0);
                mma_fp16(sacc[njp*2+1], aq, b1);
            }
        }

        // mask + online softmax
        float rmax[2] = {-1e30f, -1e30f};
        #pragma unroll
        for (int nt = 0; nt < 16; nt++)
            #pragma unroll
            for (int e = 0; e < 4; e++) {
                int col = kv0 + nt * 8 + qi * 2 + (e & 1);
                float v = sacc[nt][e] + ((4 * col + 3 < xl) ? 0.f : -1e10f);
                sacc[nt][e] = v;
                rmax[e >> 1] = fmaxf(rmax[e >> 1], v);
            }
        #pragma unroll
        for (int s2 = 1; s2 < 4; s2 <<= 1) {
            rmax[0] = fmaxf(rmax[0], __shfl_xor_sync(0xffffffff, rmax[0], s2));
            rmax[1] = fmaxf(rmax[1], __shfl_xor_sync(0xffffffff, rmax[1], s2));
        }
        float mn0 = fmaxf(mrow[0], rmax[0]), mn1 = fmaxf(mrow[1], rmax[1]);
        float sc0 = expf(mrow[0] - mn0), sc1 = expf(mrow[1] - mn1);
        float rsum[2] = {0.f, 0.f};
        #pragma unroll
        for (int nt = 0; nt < 16; nt++)
            #pragma unroll
            for (int e = 0; e < 4; e++) {
                float v = expf(sacc[nt][e] - ((e >> 1) ? mn1 : mn0));
                sacc[nt][e] = v;
                rsum[e >> 1] += v;
            }
        #pragma unroll
        for (int s2 = 1; s2 < 4; s2 <<= 1) {
            rsum[0] += __shfl_xor_sync(0xffffffff, rsum[0], s2);
            rsum[1] += __shfl_xor_sync(0xffffffff, rsum[1], s2);
        }
        lrow[0] = lrow[0] * sc0 + rsum[0];
        lrow[1] = lrow[1] * sc1 + rsum[1];
        mrow[0] = mn0; mrow[1] = mn1;
        #pragma unroll
        for (int nt = 0; nt < 16; nt++) {
            oacc[nt][0] *= sc0; oacc[nt][1] *= sc0;
            oacc[nt][2] *= sc1; oacc[nt][3] *= sc1;
        }

        // O += P @ V   (P fragments built in-register from sacc)
        #pragma unroll
        for (int j = 0; j < 8; j++) {
            u32 af[4];
            af[0] = packh2(sacc[2*j][0],   sacc[2*j][1]);
            af[1] = packh2(sacc[2*j][2],   sacc[2*j][3]);
            af[2] = packh2(sacc[2*j+1][0], sacc[2*j+1][1]);
            af[3] = packh2(sacc[2*j+1][2], sacc[2*j+1][3]);
            #pragma unroll
            for (int njp = 0; njp < 8; njp++) {
                int g = lane >> 3;
                int row = njp * 16 + ((g >> 1) << 3) + (lane & 7);
                int col = j * 16 + ((g & 1) << 3);
                u32 t[4];
                ldsm4(t, sV + (u32)(row * FP2 + col) * 2);
                u32 b0[2] = {t[0], t[1]}, b1[2] = {t[2], t[3]};
                mma_fp16(oacc[njp*2],   af, b0);
                mma_fp16(oacc[njp*2+1], af, b1);
            }
        }
    }

    float inv0 = 1.f / lrow[0], inv1 = 1.f / lrow[1];
    half* op = g_o + ((ll)(b * S + m0 + wm)) * D + h * 128;
    #pragma unroll
    for (int nt = 0; nt < 16; nt++)
        #pragma unroll
        for (int pe = 0; pe < 2; pe++) {
            int row = quad + pe * 8;
            float iv = pe ? inv1 : inv0;
            u32 pk = packh2(oacc[nt][pe*2] * iv, oacc[nt][pe*2+1] * iv);
            *(u32*)&op[(ll)row * D + nt * 8 + qi * 2] = pk;
        }
}

// ---------------- weight convert fp32 -> fp16 ----------------
__global__ void cvt_k(const float* __restrict__ in, half* __restrict__ out, ll n) {
    ll i = ((ll)blockIdx.x * 256 + threadIdx.x) * 4;
    if (i >= n) return;
    float4 v = *(const float4*)&in[i];
    out[i+0] = __float2half_rn(v.x);
    out[i+1] = __float2half_rn(v.y);
    out[i+2] = __float2half_rn(v.z);
    out[i+3] = __float2half_rn(v.w);
}

// ---------------- im2col ----------------
__global__ void im2col1_k(const float* __restrict__ x) {
    int idx = blockIdx.x * 256 + threadIdx.x;
    const int total = Bn * T1 * 384;
    if (idx >= total) return;
    int r = idx % 384;
    int t = (idx / 384) % T1;
    int b = idx / (384 * T1);
    int i = r / 3, kk = r % 3;
    int pos = 2 * t + kk - 1;
    float v = (pos >= 0 && pos < TIN) ? x[((ll)b * NMELS + i) * TIN + pos] : 0.f;
    g_col[idx] = __float2half_rn(v);
}
__global__ void im2col2_k() {
    ll idx = (ll)blockIdx.x * 256 + threadIdx.x;
    const ll total = (ll)Bn * S * 3072;
    if (idx >= total) return;
    int r = (int)(idx % 3072);
    int t = (int)((idx / 3072) % S);
    int b = (int)(idx / ((ll)S * 3072));
    int i = r / 3, kk = r % 3;
    int pos = 2 * t + kk - 1;
    g_col[idx] = (pos >= 0 && pos < T1) ? g_h1[((ll)b * T1 + pos) * D + i] : __float2half_rn(0.f);
}

// ---------------- LayerNorm -> fp16 ----------------
__global__ void ln_k(const float* __restrict__ x,
                     const float* __restrict__ w, const float* __restrict__ b) {
    int row = blockIdx.x;
    int tid = threadIdx.x;
    const float* xr = x + (ll)row * D;
    __shared__ float red[256];
    float v[4];
    #pragma unroll
    for (int i = 0; i < 4; i++) v[i] = xr[tid + 256 * i];
    float s = v[0] + v[1] + v[2] + v[3];
    red[tid] = s; __syncthreads();
    for (int o = 128; o > 0; o >>= 1) { if (tid < o) red[tid] += red[tid + o]; __syncthreads(); }
    float mean = red[0] * (1.f / D);
    __syncthreads();
    float sq = 0.f;
    #pragma unroll
    for (int i = 0; i < 4; i++) { float d0 = v[i] - mean; sq += d0 * d0; }
    red[tid] = sq; __syncthreads();
    for (int o = 128; o > 0; o >>= 1) { if (tid < o) red[tid] += red[tid + o]; __syncthreads(); }
    float rstd = rsqrtf(red[0] * (1.f / D) + 1e-5f);
    #pragma unroll
    for (int i = 0; i < 4; i++) {
        int c = tid + 256 * i;
        float y = (v[i] - mean) * rstd * w[c] + b[c];
        g_y[(ll)row * D + c] = __float2half_rn(y);
    }
}

// ---------------- output ----------------
__global__ void out_k(float* __restrict__ out, const int* __restrict__ x_len, ll out_size) {
    ll i = (ll)blockIdx.x * 256 + threadIdx.x;
    const ll nh = (ll)NTOK * D;
    if (i < nh && i < out_size) out[i] = g_x[i];
    if (i < Bn) {
        ll pos = nh + i;
        if (pos < out_size) {
            int yl = (x_len[i] + 1) / 2;
            yl = (yl + 1) / 2;
            out[pos] = (float)yl;
        }
    }
}

// ---------------- host launcher ----------------
extern "C" void kernel_launch(void* const* d_in, const int* in_sizes, int n_in,
                              void* d_out, int out_size) {
    const float* x        = (const float*)d_in[0];
    const int*   x_len    = (const int*)  d_in[1];
    const float* conv1_w  = (const float*)d_in[2];
    const float* conv1_b  = (const float*)d_in[3];
    const float* conv2_w  = (const float*)d_in[4];
    const float* conv2_b  = (const float*)d_in[5];
    const float* attn_ln_w= (const float*)d_in[6];
    const float* attn_ln_b= (const float*)d_in[7];
    const float* q_w      = (const float*)d_in[8];
    const float* q_b      = (const float*)d_in[9];
    const float* k_w      = (const float*)d_in[10];
    const float* v_w      = (const float*)d_in[11];
    const float* v_b      = (const float*)d_in[12];
    const float* out_w    = (const float*)d_in[13];
    const float* out_b    = (const float*)d_in[14];
    const float* mlp_ln_w = (const float*)d_in[15];
    const float* mlp_ln_b = (const float*)d_in[16];
    const float* mlp1_w   = (const float*)d_in[17];
    const float* mlp1_b   = (const float*)d_in[18];
    const float* mlp2_w   = (const float*)d_in[19];
    const float* mlp2_b   = (const float*)d_in[20];

    cudaFuncSetAttribute(gemm_tc, cudaFuncAttributeMaxDynamicSharedMemorySize, SMEM_TOT);
    cudaFuncSetAttribute(attn_k,  cudaFuncAttributeMaxDynamicSharedMemorySize, FSM_BYTES);

    #define SYM(p, s) do { void* _t; cudaGetSymbolAddress(&_t, s); p = (decltype(p))_t; } while (0)
    float *xs;
    SYM(xs, g_x);
    half *ph1, *pc1, *pc2, *pwq, *pwk, *pwv, *pwo, *pw1, *pw2;
    half *pcol, *py, *pq, *pk, *pvt, *pm1, *po;
    SYM(ph1, g_h1);
    SYM(pc1, c1w); SYM(pc2, c2w);
    SYM(pwq, wq); SYM(pwk, wk); SYM(pwv, wv); SYM(pwo, wo);
    SYM(pw1, w1); SYM(pw2, w2);
    SYM(pcol, g_col); SYM(py, g_y); SYM(pq, g_q); SYM(pk, g_k);
    SYM(pvt, g_vt); SYM(pm1, g_m1); SYM(po, g_o);

    auto cvt = [&](const float* in, half* out, ll n) {
        cvt_k<<<(int)((n / 4 + 255) / 256), 256>>>(in, out, n);
    };
    cvt(conv1_w, pc1, (ll)D * 384);
    cvt(conv2_w, pc2, (ll)D * 3072);
    cvt(q_w,   pwq, (ll)Ldim * D * D);
    cvt(k_w,   pwk, (ll)Ldim * D * D);
    cvt(v_w,   pwv, (ll)Ldim * D * D);
    cvt(out_w, pwo, (ll)Ldim * D * D);
    cvt(mlp1_w, pw1, (ll)Ldim * Fdim * D);
    cvt(mlp2_w, pw2, (ll)Ldim * Fdim * D);

    auto gemm = [&](const half* A, const half* B,
                    float* C, half* Cs, const float* bias,
                    int M, int N, int K, int lda, int ldb, int ldc,
                    int nz, int zDiv,
                    ll sAo, ll sAi, ll sBo, ll sBi, ll sCo, ll sCi,
                    int biasMode, int addC, int act, int transStore,
                    int outF32, int outHalf) {
        GemmP p;
        p.A = A; p.B = B;
        p.C = C; p.Cs = Cs; p.bias = bias;
        p.K = K; p.lda = lda; p.ldb = ldb; p.ldc = ldc;
        p.zDiv = zDiv;
        p.sAo = sAo; p.sAi = sAi; p.sBo = sBo; p.sBi = sBi; p.sCo = sCo; p.sCi = sCi;
        p.biasMode = biasMode; p.addC = addC; p.act = act;
        p.transStore = transStore;
        p.outF32 = outF32; p.outHalf = outHalf;
        dim3 g(N / 128, M / 128, nz);
        gemm_tc<<<g, 512, SMEM_TOT>>>(p);
    };

    const ll SD = (ll)S * D;

    // conv1
    im2col1_k<<<(Bn * T1 * 384 + 255) / 256, 256>>>(x);
    gemm(pcol, pc1, 0, ph1, conv1_b,
         T1, 1024, 384, 384, 384, D,
         Bn, 1, (ll)T1 * 384, 0, 0, 0, (ll)T1 * D, 0,
         1, 0, 1, 0, 0, 1);

    // conv2
    im2col2_k<<<(int)(((ll)Bn * S * 3072 + 255) / 256), 256>>>();
    gemm(pcol, pc2, xs, 0, conv2_b,
         S, 1024, 3072, 3072, 3072, D,
         Bn, 1, (ll)S * 3072, 0, 0, 0, SD, 0,
         1, 0, 1, 0, 1, 0);

    for (int l = 0; l < 6; l++) {
        const float* aw = attn_ln_w + l * D;  const float* ab = attn_ln_b + l * D;
        const float* qb = q_b + l * D;
        const float* vb = v_b + l * D;
        const float* ob = out_b + l * D;
        const float* mw = mlp_ln_w + l * D;   const float* mb2 = mlp_ln_b + l * D;
        const float* b1 = mlp1_b + l * Fdim;
        const float* b2 = mlp2_b + l * D;
        ll wOff = (ll)l * D * D;
        ll mOff = (ll)l * Fdim * D;

        ln_k<<<NTOK, 256>>>(xs, aw, ab);

        // q, k (RoPE+scale epilogue, fp16); v (transposed [d][tok], fp16)
        gemm(py, pwq + wOff, 0, pq, qb,
             NTOK, D, D, D, D, D, 1, 1, 0,0,0,0,0,0, 1, 0, 2, 0, 0, 1);
        gemm(py, pwk + wOff, 0, pk, 0,
             NTOK, D, D, D, D, D, 1, 1, 0,0,0,0,0,0, 0, 0, 2, 0, 0, 1);
        gemm(py, pwv + wOff, 0, pvt, vb,
             NTOK, D, D, D, D, NTOK, 1, 1, 0,0,0,0,0,0, 1, 0, 0, 1, 0, 1);

        // fused flash attention -> g_o fp16
        attn_k<<<dim3(S / 64, Bn * H), 128, FSM_BYTES>>>(x_len);

        // out projection + residual
        gemm(po, pwo + wOff, xs, 0, ob,
             NTOK, D, D, D, D, D, 1, 1, 0,0,0,0,0,0, 1, 1, 0, 0, 1, 0);

        // MLP
        ln_k<<<NTOK, 256>>>(xs, mw, mb2);
        gemm(py, pw1 + mOff, 0, pm1, b1,
             NTOK, Fdim, D, D, D, Fdim, 1, 1, 0,0,0,0,0,0, 1, 0, 1, 0, 0, 1);
        gemm(pm1, pw2 + mOff, xs, 0, b2,
             NTOK, D, Fdim, Fdim, Fdim, D, 1, 1, 0,0,0,0,0,0, 1, 1, 0, 0, 1, 0);
    }

    ll nh = (ll)NTOK * D;
    out_k<<<(int)((nh + 255) / 256), 256>>>((float*)d_out, x_len, (ll)out_size);
}